// round 2
// baseline (speedup 1.0000x reference)
#include <cuda_runtime.h>
#include <math.h>
#include <stdint.h>

// ---------------- constants ----------------
#define T_LEN 512
#define BATCH 32
#define EMB   41
#define HID   800
#define G4    3200          // 4*HID
#define IN0   42            // EMB+1
#define IN1   1600          // 2*HID
#define UNITS 20

// ---------------- device scratch (static, no allocations) ----------------
__device__ float g_xw[2u * T_LEN * BATCH * G4];   // [dir][t*32+b][3200]
__device__ float g_h0[T_LEN * BATCH * IN1];       // [t*32+b][1600] fwd|bwd
__device__ float g_h1[T_LEN * BATCH * IN1];
__device__ float g_c[2 * BATCH * HID];            // [dir][b][HID]
__device__ float g_ang[T_LEN * BATCH * 3];

// per-direction grid barrier state
__device__ unsigned g_barcnt[2];
__device__ unsigned g_bargen[2];

__device__ __forceinline__ float sigf(float x) { return 1.0f / (1.0f + expf(-x)); }

// packed fp32x2 FMA (Blackwell FFMA2) — d += a * b elementwise on 2 lanes
__device__ __forceinline__ void fma2(unsigned long long& d,
                                     unsigned long long a,
                                     unsigned long long b) {
    asm("fma.rn.f32x2 %0, %1, %2, %0;" : "+l"(d) : "l"(a), "l"(b));
}
__device__ __forceinline__ float2 unpack2(unsigned long long v) {
    float2 r;
    asm("mov.b64 {%0, %1}, %2;" : "=f"(r.x), "=f"(r.y) : "l"(v));
    return r;
}

// ---------------- kernel: layer0 input projection ----------------
__global__ void k_xw0(const float* __restrict__ seq,
                      const float* __restrict__ w_ih,
                      const float* __restrict__ bias) {
    __shared__ float xs[BATCH * IN0];
    int t = blockIdx.y;
    int d = blockIdx.z;
    int g = blockIdx.x * 128 + threadIdx.x;

    for (int e = threadIdx.x; e < BATCH * IN0; e += 128) {
        int b = e / IN0, i = e % IN0;
        xs[e] = (i < EMB) ? seq[(size_t)(t * BATCH + b) * EMB + i] : (float)t;
    }
    __syncthreads();

    float acc[BATCH];
    float bv = bias[d * G4 + g];
#pragma unroll
    for (int b = 0; b < BATCH; b++) acc[b] = bv;

    const float* wrow = w_ih + (size_t)(d * G4 + g) * IN0;
#pragma unroll
    for (int i = 0; i < IN0; i++) {
        float wv = wrow[i];
#pragma unroll
        for (int b = 0; b < BATCH; b++) acc[b] += wv * xs[b * IN0 + i];
    }

    size_t base = ((size_t)(d * T_LEN + t) * BATCH) * G4 + g;
#pragma unroll
    for (int b = 0; b < BATCH; b++) g_xw[base + (size_t)b * G4] = acc[b];
}

// ---------------- persistent LSTM layer kernel ----------------
// grid (50, 2): blockIdx.x -> 16 hidden units (64 gate cols), blockIdx.y -> dir.
// 128 threads. Thread tile 4 batches x 4 cols, K-paired FFMA2.
__global__ void __launch_bounds__(128, 1)
k_lstm(int layer, const float* __restrict__ w_hh) {
    __shared__ float Ht[2][32][36];
    __shared__ float Wt[2][64][36];
    __shared__ float Gt[32][68];

    const int tid = threadIdx.x;
    const int d   = blockIdx.y;
    const int j0  = blockIdx.x * 16;
    const int ty  = tid >> 4;     // 0..7  (batch group)
    const int tx  = tid & 15;     // 0..15 (col group)
    const int nblk = gridDim.x;   // 50 per dir

    float* hbuf = layer ? g_h1 : g_h0;

    // fill index decomposition (Ht: 2 float4/thread, Wt: 4 float4/thread)
    const int hrow0 = tid >> 3;            // Ht rows (tid, tid+128)>>3
    const int hkq   = (tid & 7) * 4;

    for (int t = 0; t < T_LEN; t++) {
        const int tt = (d == 0) ? t : (T_LEN - 1 - t);
        const int tp = (d == 0) ? t - 1 : tt + 1;

        unsigned long long acc[4][4];
#pragma unroll
        for (int i = 0; i < 4; i++)
#pragma unroll
            for (int j = 0; j < 4; j++) acc[i][j] = 0ULL;

        if (t > 0) {
            const float* hsrc = hbuf + (size_t)tp * BATCH * IN1 + d * HID;
            const float* wsrc = w_hh + (size_t)d * G4 * HID;

            // prefetch tile 0
            float4 hreg[2], wreg[4];
#pragma unroll
            for (int r = 0; r < 2; r++) {
                int row = (tid + 128 * r) >> 3;
                hreg[r] = *(const float4*)(hsrc + (size_t)row * IN1 + hkq);
            }
#pragma unroll
            for (int r = 0; r < 4; r++) {
                int row = (tid + 128 * r) >> 3;
                int g2  = (row >> 4) * HID + j0 + (row & 15);
                wreg[r] = *(const float4*)(wsrc + (size_t)g2 * HID + hkq);
            }
#pragma unroll
            for (int r = 0; r < 2; r++) {
                int row = (tid + 128 * r) >> 3;
                *(float4*)&Ht[0][row][hkq] = hreg[r];
            }
#pragma unroll
            for (int r = 0; r < 4; r++) {
                int row = (tid + 128 * r) >> 3;
                *(float4*)&Wt[0][row][hkq] = wreg[r];
            }
            __syncthreads();

            for (int kt = 0; kt < 25; kt++) {
                const int cur = kt & 1;
                const int nk  = (kt + 1) * 32;
                if (kt + 1 < 25) {
#pragma unroll
                    for (int r = 0; r < 2; r++) {
                        int row = (tid + 128 * r) >> 3;
                        hreg[r] = *(const float4*)(hsrc + (size_t)row * IN1 + nk + hkq);
                    }
#pragma unroll
                    for (int r = 0; r < 4; r++) {
                        int row = (tid + 128 * r) >> 3;
                        int g2  = (row >> 4) * HID + j0 + (row & 15);
                        wreg[r] = *(const float4*)(wsrc + (size_t)g2 * HID + nk + hkq);
                    }
                }
#pragma unroll
                for (int kk = 0; kk < 32; kk += 4) {
                    ulonglong2 a2[4], w2[4];
#pragma unroll
                    for (int i = 0; i < 4; i++)
                        a2[i] = *(const ulonglong2*)&Ht[cur][ty * 4 + i][kk];
#pragma unroll
                    for (int j = 0; j < 4; j++)
                        w2[j] = *(const ulonglong2*)&Wt[cur][tx * 4 + j][kk];
#pragma unroll
                    for (int i = 0; i < 4; i++)
#pragma unroll
                        for (int j = 0; j < 4; j++) {
                            fma2(acc[i][j], a2[i].x, w2[j].x);
                            fma2(acc[i][j], a2[i].y, w2[j].y);
                        }
                }
                if (kt + 1 < 25) {
                    const int nxt = cur ^ 1;
#pragma unroll
                    for (int r = 0; r < 2; r++) {
                        int row = (tid + 128 * r) >> 3;
                        *(float4*)&Ht[nxt][row][hkq] = hreg[r];
                    }
#pragma unroll
                    for (int r = 0; r < 4; r++) {
                        int row = (tid + 128 * r) >> 3;
                        *(float4*)&Wt[nxt][row][hkq] = wreg[r];
                    }
                }
                __syncthreads();
            }
        }

        // finalize: add xw, stage gates in smem
        const size_t xwb = ((size_t)(d * T_LEN + tt) * BATCH) * G4;
#pragma unroll
        for (int i = 0; i < 4; i++) {
            int b = ty * 4 + i;
#pragma unroll
            for (int j = 0; j < 4; j++) {
                int cl = tx * 4 + j;
                int gc = (cl >> 4) * HID + j0 + (cl & 15);
                float2 f = unpack2(acc[i][j]);
                Gt[b][cl] = f.x + f.y + g_xw[xwb + (size_t)b * G4 + gc];
            }
        }
        __syncthreads();

        // LSTM pointwise epilogue: 512 (b, j) pairs / 128 threads = 4 each
#pragma unroll
        for (int q = 0; q < 4; q++) {
            int p  = tid + 128 * q;
            int b  = p >> 4;
            int jj = p & 15;
            float iv = Gt[b][jj];
            float fv = Gt[b][16 + jj];
            float gv = Gt[b][32 + jj];
            float ov = Gt[b][48 + jj];
            int cidx = (d * BATCH + b) * HID + j0 + jj;
            float cold = (t > 0) ? g_c[cidx] : 0.0f;
            float cn = sigf(fv) * cold + sigf(iv) * tanhf(gv);
            float hn = sigf(ov) * tanhf(cn);
            g_c[cidx] = cn;
            hbuf[((size_t)tt * BATCH + b) * IN1 + d * HID + j0 + jj] = hn;
        }

        // per-direction grid barrier
        __threadfence();
        __syncthreads();
        if (tid == 0) {
            unsigned gen = atomicAdd(&g_bargen[d], 0u);
            unsigned arrived = atomicAdd(&g_barcnt[d], 1u);
            if (arrived == (unsigned)(nblk - 1)) {
                g_barcnt[d] = 0;
                __threadfence();
                atomicExch(&g_bargen[d], gen + 1u);
            } else {
                while (atomicAdd(&g_bargen[d], 0u) == gen) { __nanosleep(32); }
            }
        }
        __syncthreads();
    }
}

// ---------------- layer1 input projection GEMM (FFMA2, double-buffered) ----
// C[m][n] = b1[n] + sum_k g_h0[m][k] * w_ih1[n][k];  M=16384, N=6400, K=1600
__global__ void __launch_bounds__(256, 1)
k_xw1(const float* __restrict__ w, const float* __restrict__ bias) {
    __shared__ float As[2][64][36];
    __shared__ float Bs[2][64][36];

    const int tid = threadIdx.x;
    const int m0 = blockIdx.y * 64;
    const int n0 = blockIdx.x * 64;
    const int tm = tid >> 4, tn = tid & 15;
    const int frow0 = tid >> 3;           // fill rows (tid, tid+256)>>3
    const int fkq   = (tid & 7) * 4;

    unsigned long long acc[4][4];
#pragma unroll
    for (int i = 0; i < 4; i++)
#pragma unroll
        for (int j = 0; j < 4; j++) acc[i][j] = 0ULL;

    float4 areg[2], breg[2];
#pragma unroll
    for (int r = 0; r < 2; r++) {
        int row = (tid + 256 * r) >> 3;
        areg[r] = *(const float4*)(g_h0 + (size_t)(m0 + row) * IN1 + fkq);
        breg[r] = *(const float4*)(w + (size_t)(n0 + row) * IN1 + fkq);
    }
#pragma unroll
    for (int r = 0; r < 2; r++) {
        int row = (tid + 256 * r) >> 3;
        *(float4*)&As[0][row][fkq] = areg[r];
        *(float4*)&Bs[0][row][fkq] = breg[r];
    }
    __syncthreads();

    for (int kt = 0; kt < 50; kt++) {
        const int cur = kt & 1;
        const int nk  = (kt + 1) * 32;
        if (kt + 1 < 50) {
#pragma unroll
            for (int r = 0; r < 2; r++) {
                int row = (tid + 256 * r) >> 3;
                areg[r] = *(const float4*)(g_h0 + (size_t)(m0 + row) * IN1 + nk + fkq);
                breg[r] = *(const float4*)(w + (size_t)(n0 + row) * IN1 + nk + fkq);
            }
        }
#pragma unroll
        for (int kk = 0; kk < 32; kk += 4) {
            ulonglong2 a2[4], b2[4];
#pragma unroll
            for (int i = 0; i < 4; i++)
                a2[i] = *(const ulonglong2*)&As[cur][tm * 4 + i][kk];
#pragma unroll
            for (int j = 0; j < 4; j++)
                b2[j] = *(const ulonglong2*)&Bs[cur][tn * 4 + j][kk];
#pragma unroll
            for (int i = 0; i < 4; i++)
#pragma unroll
                for (int j = 0; j < 4; j++) {
                    fma2(acc[i][j], a2[i].x, b2[j].x);
                    fma2(acc[i][j], a2[i].y, b2[j].y);
                }
        }
        if (kt + 1 < 50) {
            const int nxt = cur ^ 1;
#pragma unroll
            for (int r = 0; r < 2; r++) {
                int row = (tid + 256 * r) >> 3;
                *(float4*)&As[nxt][row][fkq] = areg[r];
                *(float4*)&Bs[nxt][row][fkq] = breg[r];
            }
        }
        __syncthreads();
    }

    const int dd = n0 / G4;
    const size_t dbase = (size_t)dd * ((size_t)T_LEN * BATCH * G4);
#pragma unroll
    for (int i = 0; i < 4; i++) {
        int m = m0 + tm * 4 + i;
#pragma unroll
        for (int j = 0; j < 4; j++) {
            int n = n0 + tn * 4 + j;
            float2 f = unpack2(acc[i][j]);
            g_xw[dbase + (size_t)m * G4 + (n - dd * G4)] = f.x + f.y + bias[n];
        }
    }
}

// ---------------- head: linear + softmax + angles ----------------
__global__ void k_head(const float* __restrict__ lin_w,
                       const float* __restrict__ lin_b,
                       const float* __restrict__ alpha) {
    __shared__ float sl[8][UNITS];
    int warp = threadIdx.x >> 5, lane = threadIdx.x & 31;
    int m = blockIdx.x * 8 + warp;
    const float* hrow = g_h1 + (size_t)m * IN1;

    for (int u = 0; u < UNITS; u++) {
        float s = 0.0f;
        const float* wrow = lin_w + (size_t)u * IN1;
        for (int i = lane; i < IN1; i += 32) s += hrow[i] * wrow[i];
#pragma unroll
        for (int off = 16; off; off >>= 1) s += __shfl_xor_sync(0xffffffffu, s, off);
        if (lane == 0) sl[warp][u] = s + lin_b[u];
    }
    __syncwarp();

    float v = (lane < UNITS) ? sl[warp][lane] : -INFINITY;
    float mx = v;
#pragma unroll
    for (int off = 16; off; off >>= 1) mx = fmaxf(mx, __shfl_xor_sync(0xffffffffu, mx, off));
    float e = (lane < UNITS) ? expf(v - mx) : 0.0f;
    float se = e;
#pragma unroll
    for (int off = 16; off; off >>= 1) se += __shfl_xor_sync(0xffffffffu, se, off);
    float soft = e / se;

#pragma unroll
    for (int j = 0; j < 3; j++) {
        float a = (lane < UNITS) ? alpha[lane * 3 + j] : 0.0f;
        float ss = soft * sinf(a);
        float cc = soft * cosf(a);
#pragma unroll
        for (int off = 16; off; off >>= 1) {
            ss += __shfl_xor_sync(0xffffffffu, ss, off);
            cc += __shfl_xor_sync(0xffffffffu, cc, off);
        }
        if (lane == 0) g_ang[(size_t)m * 3 + j] = atan2f(ss, cc);
    }
}

// ---------------- geometric chain ----------------
__global__ void k_geom(float* __restrict__ out) {
    int b = threadIdx.x;
    if (b >= BATCH) return;

    const float RL[3] = {1.329f, 1.459f, 1.525f};
    const float TA[3] = {2.034f, 2.119f, 1.937f};
    float cT[3], sT[3];
#pragma unroll
    for (int i = 0; i < 3; i++) { cT[i] = cosf(TA[i]); sT[i] = sinf(TA[i]); }

    float Ax = 0.f, Ay = 0.f, Az = 1.f;
    float Bx = 0.f, By = 1.f, Bz = 0.f;
    float Cx = 1.f, Cy = 0.f, Cz = 0.f;

    out[(0 * BATCH + b) * 3 + 0] = Ax; out[(0 * BATCH + b) * 3 + 1] = Ay; out[(0 * BATCH + b) * 3 + 2] = Az;
    out[(1 * BATCH + b) * 3 + 0] = Bx; out[(1 * BATCH + b) * 3 + 1] = By; out[(1 * BATCH + b) * 3 + 2] = Bz;
    out[(2 * BATCH + b) * 3 + 0] = Cx; out[(2 * BATCH + b) * 3 + 1] = Cy; out[(2 * BATCH + b) * 3 + 2] = Cz;

    for (int s = 0; s < T_LEN - 1; s++) {
        size_t abase = ((size_t)(s + 1) * BATCH + b) * 3;
#pragma unroll
        for (int i = 0; i < 3; i++) {
            float P = g_ang[abase + i];
            float d2x = -RL[i] * cT[i];
            float d2y = RL[i] * cosf(P) * sT[i];
            float d2z = RL[i] * sinf(P) * sT[i];

            float bcx = Cx - Bx, bcy = Cy - By, bcz = Cz - Bz;
            float rn = 1.0f / sqrtf(bcx * bcx + bcy * bcy + bcz * bcz);
            bcx *= rn; bcy *= rn; bcz *= rn;

            float abx = Bx - Ax, aby = By - Ay, abz = Bz - Az;
            float nx = aby * bcz - abz * bcy;
            float ny = abz * bcx - abx * bcz;
            float nz = abx * bcy - aby * bcx;
            float rn2 = 1.0f / sqrtf(nx * nx + ny * ny + nz * nz);
            nx *= rn2; ny *= rn2; nz *= rn2;

            float m1x = ny * bcz - nz * bcy;
            float m1y = nz * bcx - nx * bcz;
            float m1z = nx * bcy - ny * bcx;

            float Dx = bcx * d2x + m1x * d2y + nx * d2z + Cx;
            float Dy = bcy * d2x + m1y * d2y + ny * d2z + Cy;
            float Dz = bcz * d2x + m1z * d2y + nz * d2z + Cz;

            size_t obase = ((size_t)(3 + 3 * s + i) * BATCH + b) * 3;
            out[obase + 0] = Dx; out[obase + 1] = Dy; out[obase + 2] = Dz;

            Ax = Bx; Ay = By; Az = Bz;
            Bx = Cx; By = Cy; Bz = Cz;
            Cx = Dx; Cy = Dy; Cz = Dz;
        }
    }
}

// ---------------- launch ----------------
extern "C" void kernel_launch(void* const* d_in, const int* in_sizes, int n_in,
                              void* d_out, int out_size) {
    const float* seq   = (const float*)d_in[0];
    const float* w_ih0 = (const float*)d_in[2];
    const float* w_hh0 = (const float*)d_in[3];
    const float* b0    = (const float*)d_in[4];
    const float* w_ih1 = (const float*)d_in[5];
    const float* w_hh1 = (const float*)d_in[6];
    const float* b1    = (const float*)d_in[7];
    const float* lin_w = (const float*)d_in[8];
    const float* lin_b = (const float*)d_in[9];
    const float* alpha = (const float*)d_in[10];
    float* out = (float*)d_out;

    k_xw0<<<dim3(G4 / 128, T_LEN, 2), 128>>>(seq, w_ih0, b0);
    k_lstm<<<dim3(HID / 16, 2), 128>>>(0, w_hh0);
    k_xw1<<<dim3(6400 / 64, (T_LEN * BATCH) / 64), 256>>>(w_ih1, b1);
    k_lstm<<<dim3(HID / 16, 2), 128>>>(1, w_hh1);
    k_head<<<(T_LEN * BATCH) / 8, 256>>>(lin_w, lin_b, alpha);
    k_geom<<<1, 32>>>(out);
}

// round 3
// speedup vs baseline: 1.0025x; 1.0025x over previous
#include <cuda_runtime.h>
#include <math.h>
#include <stdint.h>

// ---------------- constants ----------------
#define T_LEN 512
#define BATCH 32
#define EMB   41
#define HID   800
#define G4    3200          // 4*HID
#define IN0   42            // EMB+1
#define IN1   1600          // 2*HID
#define UNITS 20

// ---------------- device scratch (static, no allocations) ----------------
__device__ float g_xw[2u * T_LEN * BATCH * G4];   // [dir][t*32+b][3200]
__device__ float g_h0[T_LEN * BATCH * IN1];       // [t*32+b][1600] fwd|bwd
__device__ float g_h1[T_LEN * BATCH * IN1];
__device__ float g_c[2 * BATCH * HID];            // [dir][b][HID]
__device__ float g_ang[T_LEN * BATCH * 3];

// per-direction grid barrier state
__device__ unsigned g_barcnt[2];
__device__ unsigned g_bargen[2];

__device__ __forceinline__ float sigf(float x) { return 1.0f / (1.0f + expf(-x)); }

// packed fp32x2 FMA (Blackwell FFMA2) — d += a * b elementwise on 2 lanes
__device__ __forceinline__ void fma2(unsigned long long& d,
                                     unsigned long long a,
                                     unsigned long long b) {
    asm("fma.rn.f32x2 %0, %1, %2, %0;" : "+l"(d) : "l"(a), "l"(b));
}
__device__ __forceinline__ float2 unpack2(unsigned long long v) {
    float2 r;
    asm("mov.b64 {%0, %1}, %2;" : "=f"(r.x), "=f"(r.y) : "l"(v));
    return r;
}

// ---------------- kernel: layer0 input projection ----------------
__global__ void k_xw0(const float* __restrict__ seq,
                      const float* __restrict__ w_ih,
                      const float* __restrict__ bias) {
    __shared__ float xs[BATCH * IN0];
    int t = blockIdx.y;
    int d = blockIdx.z;
    int g = blockIdx.x * 128 + threadIdx.x;

    for (int e = threadIdx.x; e < BATCH * IN0; e += 128) {
        int b = e / IN0, i = e % IN0;
        xs[e] = (i < EMB) ? seq[(size_t)(t * BATCH + b) * EMB + i] : (float)t;
    }
    __syncthreads();

    float acc[BATCH];
    float bv = bias[d * G4 + g];
#pragma unroll
    for (int b = 0; b < BATCH; b++) acc[b] = bv;

    const float* wrow = w_ih + (size_t)(d * G4 + g) * IN0;
#pragma unroll
    for (int i = 0; i < IN0; i++) {
        float wv = wrow[i];
#pragma unroll
        for (int b = 0; b < BATCH; b++) acc[b] += wv * xs[b * IN0 + i];
    }

    size_t base = ((size_t)(d * T_LEN + t) * BATCH) * G4 + g;
#pragma unroll
    for (int b = 0; b < BATCH; b++) g_xw[base + (size_t)b * G4] = acc[b];
}

// ---------------- persistent LSTM layer kernel ----------------
// grid (50, 2): blockIdx.x -> 16 hidden units (64 gate cols), blockIdx.y -> dir.
// 128 threads. Thread tile 4 batches x 4 cols, K-paired FFMA2.
__global__ void __launch_bounds__(128, 1)
k_lstm(int layer, const float* __restrict__ w_hh) {
    __shared__ float Ht[2][32][36];
    __shared__ float Wt[2][64][36];
    __shared__ float Gt[32][68];

    const int tid = threadIdx.x;
    const int d   = blockIdx.y;
    const int j0  = blockIdx.x * 16;
    const int ty  = tid >> 4;     // 0..7  (batch group)
    const int tx  = tid & 15;     // 0..15 (col group)
    const int nblk = gridDim.x;   // 50 per dir

    float* hbuf = layer ? g_h1 : g_h0;

    // fill index decomposition (Ht: 2 float4/thread, Wt: 4 float4/thread)
    const int hrow0 = tid >> 3;            // Ht rows (tid, tid+128)>>3
    const int hkq   = (tid & 7) * 4;

    for (int t = 0; t < T_LEN; t++) {
        const int tt = (d == 0) ? t : (T_LEN - 1 - t);
        const int tp = (d == 0) ? t - 1 : tt + 1;

        unsigned long long acc[4][4];
#pragma unroll
        for (int i = 0; i < 4; i++)
#pragma unroll
            for (int j = 0; j < 4; j++) acc[i][j] = 0ULL;

        if (t > 0) {
            const float* hsrc = hbuf + (size_t)tp * BATCH * IN1 + d * HID;
            const float* wsrc = w_hh + (size_t)d * G4 * HID;

            // prefetch tile 0
            float4 hreg[2], wreg[4];
#pragma unroll
            for (int r = 0; r < 2; r++) {
                int row = (tid + 128 * r) >> 3;
                hreg[r] = *(const float4*)(hsrc + (size_t)row * IN1 + hkq);
            }
#pragma unroll
            for (int r = 0; r < 4; r++) {
                int row = (tid + 128 * r) >> 3;
                int g2  = (row >> 4) * HID + j0 + (row & 15);
                wreg[r] = *(const float4*)(wsrc + (size_t)g2 * HID + hkq);
            }
#pragma unroll
            for (int r = 0; r < 2; r++) {
                int row = (tid + 128 * r) >> 3;
                *(float4*)&Ht[0][row][hkq] = hreg[r];
            }
#pragma unroll
            for (int r = 0; r < 4; r++) {
                int row = (tid + 128 * r) >> 3;
                *(float4*)&Wt[0][row][hkq] = wreg[r];
            }
            __syncthreads();

            for (int kt = 0; kt < 25; kt++) {
                const int cur = kt & 1;
                const int nk  = (kt + 1) * 32;
                if (kt + 1 < 25) {
#pragma unroll
                    for (int r = 0; r < 2; r++) {
                        int row = (tid + 128 * r) >> 3;
                        hreg[r] = *(const float4*)(hsrc + (size_t)row * IN1 + nk + hkq);
                    }
#pragma unroll
                    for (int r = 0; r < 4; r++) {
                        int row = (tid + 128 * r) >> 3;
                        int g2  = (row >> 4) * HID + j0 + (row & 15);
                        wreg[r] = *(const float4*)(wsrc + (size_t)g2 * HID + nk + hkq);
                    }
                }
#pragma unroll
                for (int kk = 0; kk < 32; kk += 4) {
                    ulonglong2 a2[4], w2[4];
#pragma unroll
                    for (int i = 0; i < 4; i++)
                        a2[i] = *(const ulonglong2*)&Ht[cur][ty * 4 + i][kk];
#pragma unroll
                    for (int j = 0; j < 4; j++)
                        w2[j] = *(const ulonglong2*)&Wt[cur][tx * 4 + j][kk];
#pragma unroll
                    for (int i = 0; i < 4; i++)
#pragma unroll
                        for (int j = 0; j < 4; j++) {
                            fma2(acc[i][j], a2[i].x, w2[j].x);
                            fma2(acc[i][j], a2[i].y, w2[j].y);
                        }
                }
                if (kt + 1 < 25) {
                    const int nxt = cur ^ 1;
#pragma unroll
                    for (int r = 0; r < 2; r++) {
                        int row = (tid + 128 * r) >> 3;
                        *(float4*)&Ht[nxt][row][hkq] = hreg[r];
                    }
#pragma unroll
                    for (int r = 0; r < 4; r++) {
                        int row = (tid + 128 * r) >> 3;
                        *(float4*)&Wt[nxt][row][hkq] = wreg[r];
                    }
                }
                __syncthreads();
            }
        }

        // finalize: add xw, stage gates in smem
        const size_t xwb = ((size_t)(d * T_LEN + tt) * BATCH) * G4;
#pragma unroll
        for (int i = 0; i < 4; i++) {
            int b = ty * 4 + i;
#pragma unroll
            for (int j = 0; j < 4; j++) {
                int cl = tx * 4 + j;
                int gc = (cl >> 4) * HID + j0 + (cl & 15);
                float2 f = unpack2(acc[i][j]);
                Gt[b][cl] = f.x + f.y + g_xw[xwb + (size_t)b * G4 + gc];
            }
        }
        __syncthreads();

        // LSTM pointwise epilogue: 512 (b, j) pairs / 128 threads = 4 each
#pragma unroll
        for (int q = 0; q < 4; q++) {
            int p  = tid + 128 * q;
            int b  = p >> 4;
            int jj = p & 15;
            float iv = Gt[b][jj];
            float fv = Gt[b][16 + jj];
            float gv = Gt[b][32 + jj];
            float ov = Gt[b][48 + jj];
            int cidx = (d * BATCH + b) * HID + j0 + jj;
            float cold = (t > 0) ? g_c[cidx] : 0.0f;
            float cn = sigf(fv) * cold + sigf(iv) * tanhf(gv);
            float hn = sigf(ov) * tanhf(cn);
            g_c[cidx] = cn;
            hbuf[((size_t)tt * BATCH + b) * IN1 + d * HID + j0 + jj] = hn;
        }

        // per-direction grid barrier
        __threadfence();
        __syncthreads();
        if (tid == 0) {
            unsigned gen = atomicAdd(&g_bargen[d], 0u);
            unsigned arrived = atomicAdd(&g_barcnt[d], 1u);
            if (arrived == (unsigned)(nblk - 1)) {
                g_barcnt[d] = 0;
                __threadfence();
                atomicExch(&g_bargen[d], gen + 1u);
            } else {
                while (atomicAdd(&g_bargen[d], 0u) == gen) { __nanosleep(32); }
            }
        }
        __syncthreads();
    }
}

// ---------------- layer1 input projection GEMM (FFMA2, double-buffered) ----
// C[m][n] = b1[n] + sum_k g_h0[m][k] * w_ih1[n][k];  M=16384, N=6400, K=1600
__global__ void __launch_bounds__(256, 1)
k_xw1(const float* __restrict__ w, const float* __restrict__ bias) {
    __shared__ float As[2][64][36];
    __shared__ float Bs[2][64][36];

    const int tid = threadIdx.x;
    const int m0 = blockIdx.y * 64;
    const int n0 = blockIdx.x * 64;
    const int tm = tid >> 4, tn = tid & 15;
    const int frow0 = tid >> 3;           // fill rows (tid, tid+256)>>3
    const int fkq   = (tid & 7) * 4;

    unsigned long long acc[4][4];
#pragma unroll
    for (int i = 0; i < 4; i++)
#pragma unroll
        for (int j = 0; j < 4; j++) acc[i][j] = 0ULL;

    float4 areg[2], breg[2];
#pragma unroll
    for (int r = 0; r < 2; r++) {
        int row = (tid + 256 * r) >> 3;
        areg[r] = *(const float4*)(g_h0 + (size_t)(m0 + row) * IN1 + fkq);
        breg[r] = *(const float4*)(w + (size_t)(n0 + row) * IN1 + fkq);
    }
#pragma unroll
    for (int r = 0; r < 2; r++) {
        int row = (tid + 256 * r) >> 3;
        *(float4*)&As[0][row][fkq] = areg[r];
        *(float4*)&Bs[0][row][fkq] = breg[r];
    }
    __syncthreads();

    for (int kt = 0; kt < 50; kt++) {
        const int cur = kt & 1;
        const int nk  = (kt + 1) * 32;
        if (kt + 1 < 50) {
#pragma unroll
            for (int r = 0; r < 2; r++) {
                int row = (tid + 256 * r) >> 3;
                areg[r] = *(const float4*)(g_h0 + (size_t)(m0 + row) * IN1 + nk + fkq);
                breg[r] = *(const float4*)(w + (size_t)(n0 + row) * IN1 + nk + fkq);
            }
        }
#pragma unroll
        for (int kk = 0; kk < 32; kk += 4) {
            ulonglong2 a2[4], b2[4];
#pragma unroll
            for (int i = 0; i < 4; i++)
                a2[i] = *(const ulonglong2*)&As[cur][tm * 4 + i][kk];
#pragma unroll
            for (int j = 0; j < 4; j++)
                b2[j] = *(const ulonglong2*)&Bs[cur][tn * 4 + j][kk];
#pragma unroll
            for (int i = 0; i < 4; i++)
#pragma unroll
                for (int j = 0; j < 4; j++) {
                    fma2(acc[i][j], a2[i].x, b2[j].x);
                    fma2(acc[i][j], a2[i].y, b2[j].y);
                }
        }
        if (kt + 1 < 50) {
            const int nxt = cur ^ 1;
#pragma unroll
            for (int r = 0; r < 2; r++) {
                int row = (tid + 256 * r) >> 3;
                *(float4*)&As[nxt][row][fkq] = areg[r];
                *(float4*)&Bs[nxt][row][fkq] = breg[r];
            }
        }
        __syncthreads();
    }

    const int dd = n0 / G4;
    const size_t dbase = (size_t)dd * ((size_t)T_LEN * BATCH * G4);
#pragma unroll
    for (int i = 0; i < 4; i++) {
        int m = m0 + tm * 4 + i;
#pragma unroll
        for (int j = 0; j < 4; j++) {
            int n = n0 + tn * 4 + j;
            float2 f = unpack2(acc[i][j]);
            g_xw[dbase + (size_t)m * G4 + (n - dd * G4)] = f.x + f.y + bias[n];
        }
    }
}

// ---------------- head: linear + softmax + angles ----------------
__global__ void k_head(const float* __restrict__ lin_w,
                       const float* __restrict__ lin_b,
                       const float* __restrict__ alpha) {
    __shared__ float sl[8][UNITS];
    int warp = threadIdx.x >> 5, lane = threadIdx.x & 31;
    int m = blockIdx.x * 8 + warp;
    const float* hrow = g_h1 + (size_t)m * IN1;

    for (int u = 0; u < UNITS; u++) {
        float s = 0.0f;
        const float* wrow = lin_w + (size_t)u * IN1;
        for (int i = lane; i < IN1; i += 32) s += hrow[i] * wrow[i];
#pragma unroll
        for (int off = 16; off; off >>= 1) s += __shfl_xor_sync(0xffffffffu, s, off);
        if (lane == 0) sl[warp][u] = s + lin_b[u];
    }
    __syncwarp();

    float v = (lane < UNITS) ? sl[warp][lane] : -INFINITY;
    float mx = v;
#pragma unroll
    for (int off = 16; off; off >>= 1) mx = fmaxf(mx, __shfl_xor_sync(0xffffffffu, mx, off));
    float e = (lane < UNITS) ? expf(v - mx) : 0.0f;
    float se = e;
#pragma unroll
    for (int off = 16; off; off >>= 1) se += __shfl_xor_sync(0xffffffffu, se, off);
    float soft = e / se;

#pragma unroll
    for (int j = 0; j < 3; j++) {
        float a = (lane < UNITS) ? alpha[lane * 3 + j] : 0.0f;
        float ss = soft * sinf(a);
        float cc = soft * cosf(a);
#pragma unroll
        for (int off = 16; off; off >>= 1) {
            ss += __shfl_xor_sync(0xffffffffu, ss, off);
            cc += __shfl_xor_sync(0xffffffffu, cc, off);
        }
        if (lane == 0) g_ang[(size_t)m * 3 + j] = atan2f(ss, cc);
    }
}

// ---------------- geometric chain ----------------
__global__ void k_geom(float* __restrict__ out) {
    int b = threadIdx.x;
    if (b >= BATCH) return;

    const float RL[3] = {1.329f, 1.459f, 1.525f};
    const float TA[3] = {2.034f, 2.119f, 1.937f};
    float cT[3], sT[3];
#pragma unroll
    for (int i = 0; i < 3; i++) { cT[i] = cosf(TA[i]); sT[i] = sinf(TA[i]); }

    float Ax = 0.f, Ay = 0.f, Az = 1.f;
    float Bx = 0.f, By = 1.f, Bz = 0.f;
    float Cx = 1.f, Cy = 0.f, Cz = 0.f;

    out[(0 * BATCH + b) * 3 + 0] = Ax; out[(0 * BATCH + b) * 3 + 1] = Ay; out[(0 * BATCH + b) * 3 + 2] = Az;
    out[(1 * BATCH + b) * 3 + 0] = Bx; out[(1 * BATCH + b) * 3 + 1] = By; out[(1 * BATCH + b) * 3 + 2] = Bz;
    out[(2 * BATCH + b) * 3 + 0] = Cx; out[(2 * BATCH + b) * 3 + 1] = Cy; out[(2 * BATCH + b) * 3 + 2] = Cz;

    for (int s = 0; s < T_LEN - 1; s++) {
        size_t abase = ((size_t)(s + 1) * BATCH + b) * 3;
#pragma unroll
        for (int i = 0; i < 3; i++) {
            float P = g_ang[abase + i];
            float d2x = -RL[i] * cT[i];
            float d2y = RL[i] * cosf(P) * sT[i];
            float d2z = RL[i] * sinf(P) * sT[i];

            float bcx = Cx - Bx, bcy = Cy - By, bcz = Cz - Bz;
            float rn = 1.0f / sqrtf(bcx * bcx + bcy * bcy + bcz * bcz);
            bcx *= rn; bcy *= rn; bcz *= rn;

            float abx = Bx - Ax, aby = By - Ay, abz = Bz - Az;
            float nx = aby * bcz - abz * bcy;
            float ny = abz * bcx - abx * bcz;
            float nz = abx * bcy - aby * bcx;
            float rn2 = 1.0f / sqrtf(nx * nx + ny * ny + nz * nz);
            nx *= rn2; ny *= rn2; nz *= rn2;

            float m1x = ny * bcz - nz * bcy;
            float m1y = nz * bcx - nx * bcz;
            float m1z = nx * bcy - ny * bcx;

            float Dx = bcx * d2x + m1x * d2y + nx * d2z + Cx;
            float Dy = bcy * d2x + m1y * d2y + ny * d2z + Cy;
            float Dz = bcz * d2x + m1z * d2y + nz * d2z + Cz;

            size_t obase = ((size_t)(3 + 3 * s + i) * BATCH + b) * 3;
            out[obase + 0] = Dx; out[obase + 1] = Dy; out[obase + 2] = Dz;

            Ax = Bx; Ay = By; Az = Bz;
            Bx = Cx; By = Cy; Bz = Cz;
            Cx = Dx; Cy = Dy; Cz = Dz;
        }
    }
}

// ---------------- launch ----------------
extern "C" void kernel_launch(void* const* d_in, const int* in_sizes, int n_in,
                              void* d_out, int out_size) {
    const float* seq   = (const float*)d_in[0];
    const float* w_ih0 = (const float*)d_in[2];
    const float* w_hh0 = (const float*)d_in[3];
    const float* b0    = (const float*)d_in[4];
    const float* w_ih1 = (const float*)d_in[5];
    const float* w_hh1 = (const float*)d_in[6];
    const float* b1    = (const float*)d_in[7];
    const float* lin_w = (const float*)d_in[8];
    const float* lin_b = (const float*)d_in[9];
    const float* alpha = (const float*)d_in[10];
    float* out = (float*)d_out;

    k_xw0<<<dim3(G4 / 128, T_LEN, 2), 128>>>(seq, w_ih0, b0);
    k_lstm<<<dim3(HID / 16, 2), 128>>>(0, w_hh0);
    k_xw1<<<dim3(6400 / 64, (T_LEN * BATCH) / 64), 256>>>(w_ih1, b1);
    k_lstm<<<dim3(HID / 16, 2), 128>>>(1, w_hh1);
    k_head<<<(T_LEN * BATCH) / 8, 256>>>(lin_w, lin_b, alpha);
    k_geom<<<1, 32>>>(out);
}

// round 5
// speedup vs baseline: 1.3242x; 1.3209x over previous
#include <cuda_runtime.h>
#include <cuda_bf16.h>
#include <math.h>
#include <stdint.h>

#define T_LEN 512
#define BATCH 32
#define EMB   41
#define HID   800
#define G4    3200
#define IN0   42
#define IN1   1600
#define UNITS 20
#define MTOT  (T_LEN*BATCH)   // 16384
#define NTOT  6400
#define KTOT  1600

// ---------------- device scratch ----------------
__device__ float g_xw[2u * T_LEN * BATCH * G4];
__device__ float g_h0[MTOT * IN1];
__device__ float g_h1[MTOT * IN1];
__device__ float g_c[2 * BATCH * HID];
__device__ float g_ang[MTOT * 3];
__device__ __nv_bfloat16 g_ah[(size_t)MTOT * KTOT];
__device__ __nv_bfloat16 g_al[(size_t)MTOT * KTOT];
__device__ __nv_bfloat16 g_wh[(size_t)NTOT * KTOT];
__device__ __nv_bfloat16 g_wl[(size_t)NTOT * KTOT];
__device__ unsigned g_barcnt[2];
__device__ unsigned g_bargen[2];

__device__ __forceinline__ float sigf(float x) { return 1.0f / (1.0f + expf(-x)); }

__device__ __forceinline__ void fma2(unsigned long long& d, unsigned long long a,
                                     unsigned long long b) {
    asm("fma.rn.f32x2 %0, %1, %2, %0;" : "+l"(d) : "l"(a), "l"(b));
}
__device__ __forceinline__ float2 unpack2(unsigned long long v) {
    float2 r; asm("mov.b64 {%0, %1}, %2;" : "=f"(r.x), "=f"(r.y) : "l"(v)); return r;
}
__device__ __forceinline__ uint32_t s2u(const void* p) {
    uint32_t a; asm("{.reg .u64 t; cvta.to.shared.u64 t, %1; cvt.u32.u64 %0, t;}" : "=r"(a) : "l"(p));
    return a;
}
__device__ __forceinline__ void ldsm4(uint32_t& r0, uint32_t& r1, uint32_t& r2,
                                      uint32_t& r3, uint32_t addr) {
    asm volatile("ldmatrix.sync.aligned.m8n8.x4.shared.b16 {%0,%1,%2,%3}, [%4];"
                 : "=r"(r0), "=r"(r1), "=r"(r2), "=r"(r3) : "r"(addr));
}
__device__ __forceinline__ void mma_bf16(float* c, const uint32_t* a, const uint32_t* b) {
    asm volatile("mma.sync.aligned.m16n8k16.row.col.f32.bf16.bf16.f32 "
                 "{%0,%1,%2,%3}, {%4,%5,%6,%7}, {%8,%9}, {%0,%1,%2,%3};"
                 : "+f"(c[0]), "+f"(c[1]), "+f"(c[2]), "+f"(c[3])
                 : "r"(a[0]), "r"(a[1]), "r"(a[2]), "r"(a[3]), "r"(b[0]), "r"(b[1]));
}

// ---------------- layer0 input projection ----------------
__global__ void k_xw0(const float* __restrict__ seq, const float* __restrict__ w_ih,
                      const float* __restrict__ bias) {
    __shared__ float xs[BATCH * IN0];
    int t = blockIdx.y, d = blockIdx.z;
    int g = blockIdx.x * 128 + threadIdx.x;
    for (int e = threadIdx.x; e < BATCH * IN0; e += 128) {
        int b = e / IN0, i = e % IN0;
        xs[e] = (i < EMB) ? seq[(size_t)(t * BATCH + b) * EMB + i] : (float)t;
    }
    __syncthreads();
    float acc[BATCH];
    float bv = bias[d * G4 + g];
#pragma unroll
    for (int b = 0; b < BATCH; b++) acc[b] = bv;
    const float* wrow = w_ih + (size_t)(d * G4 + g) * IN0;
#pragma unroll
    for (int i = 0; i < IN0; i++) {
        float wv = wrow[i];
#pragma unroll
        for (int b = 0; b < BATCH; b++) acc[b] += wv * xs[b * IN0 + i];
    }
    size_t base = ((size_t)(d * T_LEN + t) * BATCH) * G4 + g;
#pragma unroll
    for (int b = 0; b < BATCH; b++) g_xw[base + (size_t)b * G4] = acc[b];
}

// ---------------- bf16 split converters ----------------
__global__ void k_cvtA() {
    size_t i = (size_t)blockIdx.x * 256 + threadIdx.x;
    if (i >= (size_t)MTOT * KTOT) return;
    float v = g_h0[i];
    __nv_bfloat16 h = __float2bfloat16(v);
    g_ah[i] = h;
    g_al[i] = __float2bfloat16(v - __bfloat162float(h));
}
__global__ void k_cvtW(const float* __restrict__ src) {
    size_t i = (size_t)blockIdx.x * 256 + threadIdx.x;
    if (i >= (size_t)NTOT * KTOT) return;
    float v = src[i];
    __nv_bfloat16 h = __float2bfloat16(v);
    g_wh[i] = h;
    g_wl[i] = __float2bfloat16(v - __bfloat162float(h));
}

// ---------------- xw1: mma.sync bf16-split GEMM ----------------
// D[m][n] = sum_k h0[m][k] * w[n][k];  M=16384, N=6400, K=1600, 3 split passes.
// Block tile 128x128x32, 256 threads = 8 warps (2 M x 4 N), warp tile 64x32.
__global__ void __launch_bounds__(256)
k_xw1_mma(const float* __restrict__ bias) {
    __shared__ __align__(1024) uint8_t sm[2 * 16384];  // [buf][A 8K | B 8K]
    const uint32_t sbase = s2u(sm);

    const int tid = threadIdx.x;
    const int lane = tid & 31, wid = tid >> 5;
    const int wm = wid >> 2, wn = wid & 3;
    const int lm = lane >> 3, lr = lane & 7;
    const int n0 = blockIdx.x * 128, m0 = blockIdx.y * 128;

    // ldmatrix address bases
    const int a_row_b = wm * 64 + (lm & 1) * 8 + lr;  // + i*16
    const int a_c_b   = (lm >> 1);                    // + 2*ks
    const int b_row_b = wn * 32 + (lm >> 1) * 8 + lr; // + p*16
    const int b_c_b   = (lm & 1);

    float acc[4][4][4];
#pragma unroll
    for (int i = 0; i < 4; i++)
#pragma unroll
        for (int j = 0; j < 4; j++)
#pragma unroll
            for (int q = 0; q < 4; q++) acc[i][j][q] = 0.0f;

    // fill decomposition: 512 16B chunks per operand, 2 per thread
    const int f_row0 = tid >> 2, f_c0 = tid & 3;
    const int f_row1 = (tid + 256) >> 2, f_c1 = tid & 3;
    const int f_sc0 = f_c0 ^ ((f_row0 >> 1) & 3);
    const int f_sc1 = f_c1 ^ ((f_row1 >> 1) & 3);

    // initial fill (it = 0: pass 0, kt 0)
    {
        const __nv_bfloat16* pa = g_ah + (size_t)m0 * KTOT;
        const __nv_bfloat16* pb = g_wh + (size_t)n0 * KTOT;
        *(uint4*)(sm + f_row0 * 64 + f_sc0 * 16) = *(const uint4*)(pa + (size_t)f_row0 * KTOT + f_c0 * 8);
        *(uint4*)(sm + f_row1 * 64 + f_sc1 * 16) = *(const uint4*)(pa + (size_t)f_row1 * KTOT + f_c1 * 8);
        *(uint4*)(sm + 8192 + f_row0 * 64 + f_sc0 * 16) = *(const uint4*)(pb + (size_t)f_row0 * KTOT + f_c0 * 8);
        *(uint4*)(sm + 8192 + f_row1 * 64 + f_sc1 * 16) = *(const uint4*)(pb + (size_t)f_row1 * KTOT + f_c1 * 8);
    }
    __syncthreads();

    for (int it = 0; it < 150; it++) {
        const int cur = it & 1;
        uint4 ra0, ra1, rb0, rb1;
        if (it + 1 < 150) {
            const int nit = it + 1;
            const int pass = nit / 50, kt = nit - pass * 50;
            const int koff = kt * 32;
            const __nv_bfloat16* pa = (pass == 2 ? g_al : g_ah) + (size_t)m0 * KTOT + koff;
            const __nv_bfloat16* pb = (pass == 1 ? g_wl : g_wh) + (size_t)n0 * KTOT + koff;
            ra0 = *(const uint4*)(pa + (size_t)f_row0 * KTOT + f_c0 * 8);
            ra1 = *(const uint4*)(pa + (size_t)f_row1 * KTOT + f_c1 * 8);
            rb0 = *(const uint4*)(pb + (size_t)f_row0 * KTOT + f_c0 * 8);
            rb1 = *(const uint4*)(pb + (size_t)f_row1 * KTOT + f_c1 * 8);
        }

        const uint32_t abase = sbase + cur * 16384;
        const uint32_t bbase = abase + 8192;
#pragma unroll
        for (int ks = 0; ks < 2; ks++) {
            uint32_t af[4][4], bf[4][2];
#pragma unroll
            for (int i = 0; i < 4; i++) {
                int row = a_row_b + i * 16;
                int c = (2 * ks + a_c_b) ^ ((row >> 1) & 3);
                ldsm4(af[i][0], af[i][1], af[i][2], af[i][3], abase + row * 64 + c * 16);
            }
#pragma unroll
            for (int p = 0; p < 2; p++) {
                int row = b_row_b + p * 16;
                int c = (2 * ks + b_c_b) ^ ((row >> 1) & 3);
                ldsm4(bf[p * 2][0], bf[p * 2][1], bf[p * 2 + 1][0], bf[p * 2 + 1][1],
                      bbase + row * 64 + c * 16);
            }
#pragma unroll
            for (int i = 0; i < 4; i++)
#pragma unroll
                for (int j = 0; j < 4; j++) mma_bf16(acc[i][j], af[i], bf[j]);
        }

        if (it + 1 < 150) {
            uint8_t* dst = sm + ((it + 1) & 1) * 16384;
            *(uint4*)(dst + f_row0 * 64 + f_sc0 * 16) = ra0;
            *(uint4*)(dst + f_row1 * 64 + f_sc1 * 16) = ra1;
            *(uint4*)(dst + 8192 + f_row0 * 64 + f_sc0 * 16) = rb0;
            *(uint4*)(dst + 8192 + f_row1 * 64 + f_sc1 * 16) = rb1;
        }
        __syncthreads();
    }

    // epilogue: write acc + bias into g_xw
    const int dd = n0 / G4;
    const size_t dbase = (size_t)dd * ((size_t)MTOT * G4);
#pragma unroll
    for (int i = 0; i < 4; i++) {
        int mrow = m0 + wm * 64 + i * 16 + (lane >> 2);
#pragma unroll
        for (int j = 0; j < 4; j++) {
            int n = n0 + wn * 32 + j * 8 + (lane & 3) * 2;
            int gc = n - dd * G4;
            float2 bv = *(const float2*)(bias + n);
            float2 o0 = { acc[i][j][0] + bv.x, acc[i][j][1] + bv.y };
            float2 o1 = { acc[i][j][2] + bv.x, acc[i][j][3] + bv.y };
            *(float2*)(g_xw + dbase + (size_t)mrow * G4 + gc) = o0;
            *(float2*)(g_xw + dbase + (size_t)(mrow + 8) * G4 + gc) = o1;
        }
    }
}

// ---------------- persistent LSTM layer (256 thr, K-split halves) ---------
__global__ void __launch_bounds__(256, 1)
k_lstm(int layer, const float* __restrict__ w_hh) {
    __shared__ float Ht[2][32][36];
    __shared__ float Wt[2][64][36];
    __shared__ float Gt[2][32][68];

    const int tid = threadIdx.x;
    const int half = tid >> 7, lt = tid & 127;
    const int d = blockIdx.y, j0 = blockIdx.x * 16;
    const int ty = lt >> 4, tx = lt & 15;
    const int nblk = gridDim.x;
    const int nchunk = half ? 12 : 13;
    const int kbase = half ? 13 * 32 : 0;

    float* hbuf = layer ? g_h1 : g_h0;

    for (int t = 0; t < T_LEN; t++) {
        const int tt = (d == 0) ? t : (T_LEN - 1 - t);
        const int tp = (d == 0) ? t - 1 : tt + 1;

        unsigned long long acc[4][4];
#pragma unroll
        for (int i = 0; i < 4; i++)
#pragma unroll
            for (int j = 0; j < 4; j++) acc[i][j] = 0ULL;

        if (t > 0) {
            const float* hsrc = hbuf + (size_t)tp * BATCH * IN1 + d * HID + kbase;
            const float* wsrc = w_hh + (size_t)d * G4 * HID + kbase;
            for (int it = 0; it < 13; it++) {
                const bool act = it < nchunk;
                const int kk0 = it * 32;
                if (act) {
#pragma unroll
                    for (int r = 0; r < 2; r++) {
                        int e = lt + 128 * r;
                        int row = e >> 3, cq = (e & 7) * 4;
                        *(float4*)&Ht[half][row][cq] =
                            *(const float4*)(hsrc + (size_t)row * IN1 + kk0 + cq);
                    }
#pragma unroll
                    for (int r = 0; r < 4; r++) {
                        int e = lt + 128 * r;
                        int row = e >> 3, cq = (e & 7) * 4;
                        int g2 = (row >> 4) * HID + j0 + (row & 15);
                        *(float4*)&Wt[half][row][cq] =
                            *(const float4*)(wsrc + (size_t)g2 * HID + kk0 + cq);
                    }
                }
                __syncthreads();
                if (act) {
#pragma unroll
                    for (int kk = 0; kk < 32; kk += 4) {
                        ulonglong2 a2[4], w2[4];
#pragma unroll
                        for (int i = 0; i < 4; i++)
                            a2[i] = *(const ulonglong2*)&Ht[half][ty * 4 + i][kk];
#pragma unroll
                        for (int j = 0; j < 4; j++)
                            w2[j] = *(const ulonglong2*)&Wt[half][tx * 4 + j][kk];
#pragma unroll
                        for (int i = 0; i < 4; i++)
#pragma unroll
                            for (int j = 0; j < 4; j++) {
                                fma2(acc[i][j], a2[i].x, w2[j].x);
                                fma2(acc[i][j], a2[i].y, w2[j].y);
                            }
                    }
                }
                __syncthreads();
            }
        }

#pragma unroll
        for (int i = 0; i < 4; i++)
#pragma unroll
            for (int j = 0; j < 4; j++) {
                float2 f = unpack2(acc[i][j]);
                Gt[half][ty * 4 + i][tx * 4 + j] = f.x + f.y;
            }
        __syncthreads();

        const size_t xwb = ((size_t)(d * T_LEN + tt) * BATCH) * G4;
#pragma unroll
        for (int q = 0; q < 2; q++) {
            int p = tid + 256 * q;
            int b = p >> 4, jj = p & 15;
            float gate[4];
#pragma unroll
            for (int e = 0; e < 4; e++) {
                int cl = e * 16 + jj;
                int gc = e * HID + j0 + jj;
                float r = g_xw[xwb + (size_t)b * G4 + gc];
                if (t > 0) r += Gt[0][b][cl] + Gt[1][b][cl];
                gate[e] = r;
            }
            int cidx = (d * BATCH + b) * HID + j0 + jj;
            float cold = (t > 0) ? g_c[cidx] : 0.0f;
            float cn = sigf(gate[1]) * cold + sigf(gate[0]) * tanhf(gate[2]);
            float hn = sigf(gate[3]) * tanhf(cn);
            g_c[cidx] = cn;
            hbuf[((size_t)tt * BATCH + b) * IN1 + d * HID + j0 + jj] = hn;
        }

        __threadfence();
        __syncthreads();
        if (tid == 0) {
            unsigned gen = atomicAdd(&g_bargen[d], 0u);
            unsigned arrived = atomicAdd(&g_barcnt[d], 1u);
            if (arrived == (unsigned)(nblk - 1)) {
                g_barcnt[d] = 0;
                __threadfence();
                atomicExch(&g_bargen[d], gen + 1u);
            } else {
                while (atomicAdd(&g_bargen[d], 0u) == gen) { __nanosleep(32); }
            }
        }
        __syncthreads();
    }
}

// ---------------- head ----------------
__global__ void k_head(const float* __restrict__ lin_w, const float* __restrict__ lin_b,
                       const float* __restrict__ alpha) {
    __shared__ float sl[8][UNITS];
    int warp = threadIdx.x >> 5, lane = threadIdx.x & 31;
    int m = blockIdx.x * 8 + warp;
    const float* hrow = g_h1 + (size_t)m * IN1;
    for (int u = 0; u < UNITS; u++) {
        float s = 0.0f;
        const float* wrow = lin_w + (size_t)u * IN1;
        for (int i = lane; i < IN1; i += 32) s += hrow[i] * wrow[i];
#pragma unroll
        for (int off = 16; off; off >>= 1) s += __shfl_xor_sync(0xffffffffu, s, off);
        if (lane == 0) sl[warp][u] = s + lin_b[u];
    }
    __syncwarp();
    float v = (lane < UNITS) ? sl[warp][lane] : -INFINITY;
    float mx = v;
#pragma unroll
    for (int off = 16; off; off >>= 1) mx = fmaxf(mx, __shfl_xor_sync(0xffffffffu, mx, off));
    float e = (lane < UNITS) ? expf(v - mx) : 0.0f;
    float se = e;
#pragma unroll
    for (int off = 16; off; off >>= 1) se += __shfl_xor_sync(0xffffffffu, se, off);
    float soft = e / se;
#pragma unroll
    for (int j = 0; j < 3; j++) {
        float a = (lane < UNITS) ? alpha[lane * 3 + j] : 0.0f;
        float ss = soft * sinf(a), cc = soft * cosf(a);
#pragma unroll
        for (int off = 16; off; off >>= 1) {
            ss += __shfl_xor_sync(0xffffffffu, ss, off);
            cc += __shfl_xor_sync(0xffffffffu, cc, off);
        }
        if (lane == 0) g_ang[(size_t)m * 3 + j] = atan2f(ss, cc);
    }
}

// ---------------- geometric chain ----------------
__global__ void k_geom(float* __restrict__ out) {
    int b = threadIdx.x;
    if (b >= BATCH) return;
    const float RL[3] = {1.329f, 1.459f, 1.525f};
    const float TA[3] = {2.034f, 2.119f, 1.937f};
    float cT[3], sT[3];
#pragma unroll
    for (int i = 0; i < 3; i++) { cT[i] = cosf(TA[i]); sT[i] = sinf(TA[i]); }
    float Ax = 0.f, Ay = 0.f, Az = 1.f;
    float Bx = 0.f, By = 1.f, Bz = 0.f;
    float Cx = 1.f, Cy = 0.f, Cz = 0.f;
    out[(0 * BATCH + b) * 3 + 0] = Ax; out[(0 * BATCH + b) * 3 + 1] = Ay; out[(0 * BATCH + b) * 3 + 2] = Az;
    out[(1 * BATCH + b) * 3 + 0] = Bx; out[(1 * BATCH + b) * 3 + 1] = By; out[(1 * BATCH + b) * 3 + 2] = Bz;
    out[(2 * BATCH + b) * 3 + 0] = Cx; out[(2 * BATCH + b) * 3 + 1] = Cy; out[(2 * BATCH + b) * 3 + 2] = Cz;
    for (int s = 0; s < T_LEN - 1; s++) {
        size_t abase = ((size_t)(s + 1) * BATCH + b) * 3;
#pragma unroll
        for (int i = 0; i < 3; i++) {
            float P = g_ang[abase + i];
            float d2x = -RL[i] * cT[i];
            float d2y = RL[i] * cosf(P) * sT[i];
            float d2z = RL[i] * sinf(P) * sT[i];
            float bcx = Cx - Bx, bcy = Cy - By, bcz = Cz - Bz;
            float rn = 1.0f / sqrtf(bcx * bcx + bcy * bcy + bcz * bcz);
            bcx *= rn; bcy *= rn; bcz *= rn;
            float abx = Bx - Ax, aby = By - Ay, abz = Bz - Az;
            float nx = aby * bcz - abz * bcy;
            float ny = abz * bcx - abx * bcz;
            float nz = abx * bcy - aby * bcx;
            float rn2 = 1.0f / sqrtf(nx * nx + ny * ny + nz * nz);
            nx *= rn2; ny *= rn2; nz *= rn2;
            float m1x = ny * bcz - nz * bcy;
            float m1y = nz * bcx - nx * bcz;
            float m1z = nx * bcy - ny * bcx;
            float Dx = bcx * d2x + m1x * d2y + nx * d2z + Cx;
            float Dy = bcy * d2x + m1y * d2y + ny * d2z + Cy;
            float Dz = bcz * d2x + m1z * d2y + nz * d2z + Cz;
            size_t obase = ((size_t)(3 + 3 * s + i) * BATCH + b) * 3;
            out[obase + 0] = Dx; out[obase + 1] = Dy; out[obase + 2] = Dz;
            Ax = Bx; Ay = By; Az = Bz;
            Bx = Cx; By = Cy; Bz = Cz;
            Cx = Dx; Cy = Dy; Cz = Dz;
        }
    }
}

// ---------------- launch ----------------
extern "C" void kernel_launch(void* const* d_in, const int* in_sizes, int n_in,
                              void* d_out, int out_size) {
    const float* seq   = (const float*)d_in[0];
    const float* w_ih0 = (const float*)d_in[2];
    const float* w_hh0 = (const float*)d_in[3];
    const float* b0    = (const float*)d_in[4];
    const float* w_ih1 = (const float*)d_in[5];
    const float* w_hh1 = (const float*)d_in[6];
    const float* b1    = (const float*)d_in[7];
    const float* lin_w = (const float*)d_in[8];
    const float* lin_b = (const float*)d_in[9];
    const float* alpha = (const float*)d_in[10];
    float* out = (float*)d_out;

    k_xw0<<<dim3(G4 / 128, T_LEN, 2), 128>>>(seq, w_ih0, b0);
    k_cvtW<<<(NTOT * KTOT + 255) / 256, 256>>>(w_ih1);
    k_lstm<<<dim3(HID / 16, 2), 256>>>(0, w_hh0);
    k_cvtA<<<(MTOT * KTOT + 255) / 256, 256>>>();
    k_xw1_mma<<<dim3(NTOT / 128, MTOT / 128), 256>>>(b1);
    k_lstm<<<dim3(HID / 16, 2), 256>>>(1, w_hh1);
    k_head<<<(T_LEN * BATCH) / 8, 256>>>(lin_w, lin_b, alpha);
    k_geom<<<1, 32>>>(out);
}

// round 7
// speedup vs baseline: 3.4236x; 2.5854x over previous
#include <cuda_runtime.h>
#include <cuda_bf16.h>
#include <math.h>
#include <stdint.h>

#define T_LEN 512
#define BATCH 32
#define EMB   41
#define HID   800
#define G4    3200
#define IN0   42
#define IN1   1600
#define UNITS 20
#define MTOT  (T_LEN*BATCH)   // 16384
#define NTOT  6400
#define KTOT  1600

// ---------------- device scratch ----------------
__device__ float g_xw[2u * T_LEN * BATCH * G4];
__device__ float g_c[2 * BATCH * HID];
__device__ float g_ang[MTOT * 3];
// hidden states as bf16 hi/lo splits: [m = t*32+b][1600]
__device__ __nv_bfloat16 g_h0h[(size_t)MTOT * IN1];
__device__ __nv_bfloat16 g_h0l[(size_t)MTOT * IN1];
__device__ __nv_bfloat16 g_h1h[(size_t)MTOT * IN1];
__device__ __nv_bfloat16 g_h1l[(size_t)MTOT * IN1];
// w_ih1 split
__device__ __nv_bfloat16 g_wh[(size_t)NTOT * KTOT];
__device__ __nv_bfloat16 g_wl[(size_t)NTOT * KTOT];
// w_hh split (reused between layers): [d][3200][800]
__device__ __nv_bfloat16 g_whhh[(size_t)2 * G4 * HID];
__device__ __nv_bfloat16 g_whhl[(size_t)2 * G4 * HID];
__device__ unsigned g_barcnt[2];
__device__ unsigned g_bargen[2];

__device__ __forceinline__ float sigf(float x) { return 1.0f / (1.0f + expf(-x)); }
__device__ __forceinline__ uint32_t s2u(const void* p) {
    uint32_t a; asm("{.reg .u64 t; cvta.to.shared.u64 t, %1; cvt.u32.u64 %0, t;}" : "=r"(a) : "l"(p));
    return a;
}
__device__ __forceinline__ void ldsm4(uint32_t& r0, uint32_t& r1, uint32_t& r2,
                                      uint32_t& r3, uint32_t addr) {
    asm volatile("ldmatrix.sync.aligned.m8n8.x4.shared.b16 {%0,%1,%2,%3}, [%4];"
                 : "=r"(r0), "=r"(r1), "=r"(r2), "=r"(r3) : "r"(addr));
}
__device__ __forceinline__ void mma_bf16(float* c, const uint32_t* a, const uint32_t* b) {
    asm volatile("mma.sync.aligned.m16n8k16.row.col.f32.bf16.bf16.f32 "
                 "{%0,%1,%2,%3}, {%4,%5,%6,%7}, {%8,%9}, {%0,%1,%2,%3};"
                 : "+f"(c[0]), "+f"(c[1]), "+f"(c[2]), "+f"(c[3])
                 : "r"(a[0]), "r"(a[1]), "r"(a[2]), "r"(a[3]), "r"(b[0]), "r"(b[1]));
}

// ---------------- layer0 input projection ----------------
__global__ void k_xw0(const float* __restrict__ seq, const float* __restrict__ w_ih,
                      const float* __restrict__ bias) {
    __shared__ float xs[BATCH * IN0];
    int t = blockIdx.y, d = blockIdx.z;
    int g = blockIdx.x * 128 + threadIdx.x;
    for (int e = threadIdx.x; e < BATCH * IN0; e += 128) {
        int b = e / IN0, i = e % IN0;
        xs[e] = (i < EMB) ? seq[(size_t)(t * BATCH + b) * EMB + i] : (float)t;
    }
    __syncthreads();
    float acc[BATCH];
    float bv = bias[d * G4 + g];
#pragma unroll
    for (int b = 0; b < BATCH; b++) acc[b] = bv;
    const float* wrow = w_ih + (size_t)(d * G4 + g) * IN0;
#pragma unroll
    for (int i = 0; i < IN0; i++) {
        float wv = wrow[i];
#pragma unroll
        for (int b = 0; b < BATCH; b++) acc[b] += wv * xs[b * IN0 + i];
    }
    size_t base = ((size_t)(d * T_LEN + t) * BATCH) * G4 + g;
#pragma unroll
    for (int b = 0; b < BATCH; b++) g_xw[base + (size_t)b * G4] = acc[b];
}

// ---------------- bf16 split converter (mode 0: w_ih1, mode 1: w_hh) ------
__global__ void k_cvt(const float* __restrict__ src, int mode) {
    size_t n = mode ? (size_t)2 * G4 * HID : (size_t)NTOT * KTOT;
    __nv_bfloat16* dh = mode ? g_whhh : g_wh;
    __nv_bfloat16* dl = mode ? g_whhl : g_wl;
    size_t i = (size_t)blockIdx.x * 256 + threadIdx.x;
    if (i >= n) return;
    float v = src[i];
    __nv_bfloat16 h = __float2bfloat16(v);
    dh[i] = h;
    dl[i] = __float2bfloat16(v - __bfloat162float(h));
}

// ---------------- persistent LSTM layer: mma.sync recurrence --------------
// grid (50, 2), 256 thr (8 warps). Block: dir=blockIdx.y, 16 hid units = 64
// gate cols. W (hi+lo) resident in smem; h_prev streamed in K-chunks of 32.
#define WH_OFF 0
#define WL_OFF 103424
#define A_OFF  206848
#define GT_OFF 217088
#define LSTM_SMEM 225792

__global__ void __launch_bounds__(256, 1)
k_lstm_mma(int layer) {
    extern __shared__ __align__(16) uint8_t sm[];
    const uint32_t sbase = s2u(sm);
    const int tid = threadIdx.x, lane = tid & 31, w = tid >> 5;
    const int d = blockIdx.y, j0 = blockIdx.x * 16;
    const int nblk = gridDim.x;

    __nv_bfloat16* hh = layer ? g_h1h : g_h0h;
    __nv_bfloat16* hl = layer ? g_h1l : g_h0l;
    float* Gt = (float*)(sm + GT_OFF);   // [32][68]

    // load W slice (64 rows x 800) hi+lo into smem, padded stride 1616 B.
    // each row = 800 bf16 = 1600 B = 100 uint4 chunks (FIX: was 50).
    for (int idx = tid; idx < 12800; idx += 256) {
        int s = idx >= 6400;
        int e = idx - s * 6400;
        int r = e / 100, c = e % 100;
        int grow = (r >> 4) * HID + j0 + (r & 15);
        const __nv_bfloat16* src = (s ? g_whhl : g_whhh)
                                 + ((size_t)(d * G4 + grow) * HID + c * 8);
        *(uint4*)(sm + (s ? WL_OFF : WH_OFF) + r * 1616 + c * 16) = *(const uint4*)src;
    }
    __syncthreads();

    // ldmatrix index decomposition
    const int lr = lane & 7, q = lane >> 3;
    const int a_row = (q & 1) * 8 + lr;       // + mt*16
    const int a_kh  = (q >> 1) * 8;           // + ks*16
    const uint32_t b_base = sbase + (uint32_t)((w * 8 + lr) * 1616 + q * 16);

    // A prefetch decomposition: 1 uint4/thread, covers both splits
    const int s0 = tid >> 7, ae = tid & 127;
    const int arow = ae >> 2, ac4 = ae & 3;

    for (int t = 0; t < T_LEN; t++) {
        const int tt = d ? (T_LEN - 1 - t) : t;
        const int tp = d ? tt + 1 : t - 1;

        float acc[2][4];
#pragma unroll
        for (int mt = 0; mt < 2; mt++)
#pragma unroll
            for (int i = 0; i < 4; i++) acc[mt][i] = 0.0f;

        if (t > 0) {
            const __nv_bfloat16* asrc = (s0 ? hl : hh)
                + (size_t)(tp * BATCH + arow) * IN1 + d * HID + ac4 * 8;
            uint4 v = *(const uint4*)asrc;
            *(uint4*)(sm + A_OFF + s0 * 2560 + arow * 80 + ac4 * 16) = v;
            __syncthreads();

            for (int kc = 0; kc < 25; kc++) {
                const int cb = kc & 1;
                if (kc < 24) v = *(const uint4*)(asrc + (kc + 1) * 32);

                const uint32_t wb = b_base + (uint32_t)(kc * 64);
                uint32_t bh[4], bl[4];
                ldsm4(bh[0], bh[1], bh[2], bh[3], wb + WH_OFF);
                ldsm4(bl[0], bl[1], bl[2], bl[3], wb + WL_OFF);
#pragma unroll
                for (int ks = 0; ks < 2; ks++) {
#pragma unroll
                    for (int mt = 0; mt < 2; mt++) {
                        uint32_t ah[4], al[4];
                        uint32_t aa = sbase + A_OFF + cb * 5120
                                    + (uint32_t)((mt * 16 + a_row) * 80
                                    + (ks * 16 + a_kh) * 2);
                        ldsm4(ah[0], ah[1], ah[2], ah[3], aa);
                        ldsm4(al[0], al[1], al[2], al[3], aa + 2560);
                        mma_bf16(acc[mt], ah, &bh[ks * 2]);
                        mma_bf16(acc[mt], ah, &bl[ks * 2]);
                        mma_bf16(acc[mt], al, &bh[ks * 2]);
                    }
                }
                if (kc < 24)
                    *(uint4*)(sm + A_OFF + (cb ^ 1) * 5120 + s0 * 2560
                              + arow * 80 + ac4 * 16) = v;
                __syncthreads();
            }
        }

        // stage gates into smem
#pragma unroll
        for (int mt = 0; mt < 2; mt++) {
            int r = mt * 16 + (lane >> 2);
            int c = w * 8 + (lane & 3) * 2;
            Gt[r * 68 + c]           = acc[mt][0];
            Gt[r * 68 + c + 1]       = acc[mt][1];
            Gt[(r + 8) * 68 + c]     = acc[mt][2];
            Gt[(r + 8) * 68 + c + 1] = acc[mt][3];
        }
        __syncthreads();

        // pointwise epilogue: 512 (b, j) pairs / 256 threads
        const size_t xwb = ((size_t)(d * T_LEN + tt) * BATCH) * G4;
#pragma unroll
        for (int qq = 0; qq < 2; qq++) {
            int p = tid + 256 * qq;
            int b = p >> 4, jj = p & 15;
            const float* xr = g_xw + xwb + (size_t)b * G4 + j0 + jj;
            float g0 = Gt[b * 68 + jj]      + xr[0];
            float g1 = Gt[b * 68 + 16 + jj] + xr[HID];
            float g2 = Gt[b * 68 + 32 + jj] + xr[2 * HID];
            float g3 = Gt[b * 68 + 48 + jj] + xr[3 * HID];
            int cidx = (d * BATCH + b) * HID + j0 + jj;
            float cold = (t > 0) ? g_c[cidx] : 0.0f;
            float cn = sigf(g1) * cold + sigf(g0) * tanhf(g2);
            float hn = sigf(g3) * tanhf(cn);
            g_c[cidx] = cn;
            size_t ho = (size_t)(tt * BATCH + b) * IN1 + d * HID + j0 + jj;
            __nv_bfloat16 hhi = __float2bfloat16(hn);
            hh[ho] = hhi;
            hl[ho] = __float2bfloat16(hn - __bfloat162float(hhi));
        }

        // per-direction grid barrier
        __threadfence();
        __syncthreads();
        if (tid == 0) {
            unsigned gen = atomicAdd(&g_bargen[d], 0u);
            unsigned arrived = atomicAdd(&g_barcnt[d], 1u);
            if (arrived == (unsigned)(nblk - 1)) {
                g_barcnt[d] = 0;
                __threadfence();
                atomicExch(&g_bargen[d], gen + 1u);
            } else {
                while (atomicAdd(&g_bargen[d], 0u) == gen) { __nanosleep(32); }
            }
        }
        __syncthreads();
    }
}

// ---------------- xw1: mma.sync bf16-split GEMM ----------------
__global__ void __launch_bounds__(256)
k_xw1_mma(const float* __restrict__ bias) {
    __shared__ __align__(1024) uint8_t sm[2 * 16384];
    const uint32_t sbase = s2u(sm);

    const int tid = threadIdx.x;
    const int lane = tid & 31, wid = tid >> 5;
    const int wm = wid >> 2, wn = wid & 3;
    const int lm = lane >> 3, lr = lane & 7;
    const int n0 = blockIdx.x * 128, m0 = blockIdx.y * 128;

    const int a_row_b = wm * 64 + (lm & 1) * 8 + lr;
    const int a_c_b   = (lm >> 1);
    const int b_row_b = wn * 32 + (lm >> 1) * 8 + lr;
    const int b_c_b   = (lm & 1);

    float acc[4][4][4];
#pragma unroll
    for (int i = 0; i < 4; i++)
#pragma unroll
        for (int j = 0; j < 4; j++)
#pragma unroll
            for (int q = 0; q < 4; q++) acc[i][j][q] = 0.0f;

    const int f_row0 = tid >> 2, f_c0 = tid & 3;
    const int f_row1 = (tid + 256) >> 2, f_c1 = tid & 3;
    const int f_sc0 = f_c0 ^ ((f_row0 >> 1) & 3);
    const int f_sc1 = f_c1 ^ ((f_row1 >> 1) & 3);

    {
        const __nv_bfloat16* pa = g_h0h + (size_t)m0 * KTOT;
        const __nv_bfloat16* pb = g_wh + (size_t)n0 * KTOT;
        *(uint4*)(sm + f_row0 * 64 + f_sc0 * 16) = *(const uint4*)(pa + (size_t)f_row0 * KTOT + f_c0 * 8);
        *(uint4*)(sm + f_row1 * 64 + f_sc1 * 16) = *(const uint4*)(pa + (size_t)f_row1 * KTOT + f_c1 * 8);
        *(uint4*)(sm + 8192 + f_row0 * 64 + f_sc0 * 16) = *(const uint4*)(pb + (size_t)f_row0 * KTOT + f_c0 * 8);
        *(uint4*)(sm + 8192 + f_row1 * 64 + f_sc1 * 16) = *(const uint4*)(pb + (size_t)f_row1 * KTOT + f_c1 * 8);
    }
    __syncthreads();

    for (int it = 0; it < 150; it++) {
        const int cur = it & 1;
        uint4 ra0, ra1, rb0, rb1;
        if (it + 1 < 150) {
            const int nit = it + 1;
            const int pass = nit / 50, kt = nit - pass * 50;
            const int koff = kt * 32;
            const __nv_bfloat16* pa = (pass == 2 ? g_h0l : g_h0h) + (size_t)m0 * KTOT + koff;
            const __nv_bfloat16* pb = (pass == 1 ? g_wl : g_wh) + (size_t)n0 * KTOT + koff;
            ra0 = *(const uint4*)(pa + (size_t)f_row0 * KTOT + f_c0 * 8);
            ra1 = *(const uint4*)(pa + (size_t)f_row1 * KTOT + f_c1 * 8);
            rb0 = *(const uint4*)(pb + (size_t)f_row0 * KTOT + f_c0 * 8);
            rb1 = *(const uint4*)(pb + (size_t)f_row1 * KTOT + f_c1 * 8);
        }

        const uint32_t abase = sbase + cur * 16384;
        const uint32_t bbase = abase + 8192;
#pragma unroll
        for (int ks = 0; ks < 2; ks++) {
            uint32_t af[4][4], bf[4][2];
#pragma unroll
            for (int i = 0; i < 4; i++) {
                int row = a_row_b + i * 16;
                int c = (2 * ks + a_c_b) ^ ((row >> 1) & 3);
                ldsm4(af[i][0], af[i][1], af[i][2], af[i][3], abase + row * 64 + c * 16);
            }
#pragma unroll
            for (int p = 0; p < 2; p++) {
                int row = b_row_b + p * 16;
                int c = (2 * ks + b_c_b) ^ ((row >> 1) & 3);
                ldsm4(bf[p * 2][0], bf[p * 2][1], bf[p * 2 + 1][0], bf[p * 2 + 1][1],
                      bbase + row * 64 + c * 16);
            }
#pragma unroll
            for (int i = 0; i < 4; i++)
#pragma unroll
                for (int j = 0; j < 4; j++) mma_bf16(acc[i][j], af[i], bf[j]);
        }

        if (it + 1 < 150) {
            uint8_t* dst = sm + ((it + 1) & 1) * 16384;
            *(uint4*)(dst + f_row0 * 64 + f_sc0 * 16) = ra0;
            *(uint4*)(dst + f_row1 * 64 + f_sc1 * 16) = ra1;
            *(uint4*)(dst + 8192 + f_row0 * 64 + f_sc0 * 16) = rb0;
            *(uint4*)(dst + 8192 + f_row1 * 64 + f_sc1 * 16) = rb1;
        }
        __syncthreads();
    }

    const int dd = n0 / G4;
    const size_t dbase = (size_t)dd * ((size_t)MTOT * G4);
#pragma unroll
    for (int i = 0; i < 4; i++) {
        int mrow = m0 + wm * 64 + i * 16 + (lane >> 2);
#pragma unroll
        for (int j = 0; j < 4; j++) {
            int n = n0 + wn * 32 + j * 8 + (lane & 3) * 2;
            int gc = n - dd * G4;
            float2 bv = *(const float2*)(bias + n);
            float2 o0 = { acc[i][j][0] + bv.x, acc[i][j][1] + bv.y };
            float2 o1 = { acc[i][j][2] + bv.x, acc[i][j][3] + bv.y };
            *(float2*)(g_xw + dbase + (size_t)mrow * G4 + gc) = o0;
            *(float2*)(g_xw + dbase + (size_t)(mrow + 8) * G4 + gc) = o1;
        }
    }
}

// ---------------- head ----------------
__global__ void k_head(const float* __restrict__ lin_w, const float* __restrict__ lin_b,
                       const float* __restrict__ alpha) {
    __shared__ float sl[8][UNITS];
    int warp = threadIdx.x >> 5, lane = threadIdx.x & 31;
    int m = blockIdx.x * 8 + warp;
    const __nv_bfloat16* hrh = g_h1h + (size_t)m * IN1;
    const __nv_bfloat16* hrl = g_h1l + (size_t)m * IN1;
    for (int u = 0; u < UNITS; u++) {
        float s = 0.0f;
        const float* wrow = lin_w + (size_t)u * IN1;
        for (int i = lane; i < IN1; i += 32)
            s += (__bfloat162float(hrh[i]) + __bfloat162float(hrl[i])) * wrow[i];
#pragma unroll
        for (int off = 16; off; off >>= 1) s += __shfl_xor_sync(0xffffffffu, s, off);
        if (lane == 0) sl[warp][u] = s + lin_b[u];
    }
    __syncwarp();
    float v = (lane < UNITS) ? sl[warp][lane] : -INFINITY;
    float mx = v;
#pragma unroll
    for (int off = 16; off; off >>= 1) mx = fmaxf(mx, __shfl_xor_sync(0xffffffffu, mx, off));
    float e = (lane < UNITS) ? expf(v - mx) : 0.0f;
    float se = e;
#pragma unroll
    for (int off = 16; off; off >>= 1) se += __shfl_xor_sync(0xffffffffu, se, off);
    float soft = e / se;
#pragma unroll
    for (int j = 0; j < 3; j++) {
        float a = (lane < UNITS) ? alpha[lane * 3 + j] : 0.0f;
        float ss = soft * sinf(a), cc = soft * cosf(a);
#pragma unroll
        for (int off = 16; off; off >>= 1) {
            ss += __shfl_xor_sync(0xffffffffu, ss, off);
            cc += __shfl_xor_sync(0xffffffffu, cc, off);
        }
        if (lane == 0) g_ang[(size_t)m * 3 + j] = atan2f(ss, cc);
    }
}

// ---------------- geometric chain ----------------
__global__ void k_geom(float* __restrict__ out) {
    int b = threadIdx.x;
    if (b >= BATCH) return;
    const float RL[3] = {1.329f, 1.459f, 1.525f};
    const float TA[3] = {2.034f, 2.119f, 1.937f};
    float cT[3], sT[3];
#pragma unroll
    for (int i = 0; i < 3; i++) { cT[i] = cosf(TA[i]); sT[i] = sinf(TA[i]); }
    float Ax = 0.f, Ay = 0.f, Az = 1.f;
    float Bx = 0.f, By = 1.f, Bz = 0.f;
    float Cx = 1.f, Cy = 0.f, Cz = 0.f;
    out[(0 * BATCH + b) * 3 + 0] = Ax; out[(0 * BATCH + b) * 3 + 1] = Ay; out[(0 * BATCH + b) * 3 + 2] = Az;
    out[(1 * BATCH + b) * 3 + 0] = Bx; out[(1 * BATCH + b) * 3 + 1] = By; out[(1 * BATCH + b) * 3 + 2] = Bz;
    out[(2 * BATCH + b) * 3 + 0] = Cx; out[(2 * BATCH + b) * 3 + 1] = Cy; out[(2 * BATCH + b) * 3 + 2] = Cz;
    for (int s = 0; s < T_LEN - 1; s++) {
        size_t abase = ((size_t)(s + 1) * BATCH + b) * 3;
#pragma unroll
        for (int i = 0; i < 3; i++) {
            float P = g_ang[abase + i];
            float d2x = -RL[i] * cT[i];
            float d2y = RL[i] * cosf(P) * sT[i];
            float d2z = RL[i] * sinf(P) * sT[i];
            float bcx = Cx - Bx, bcy = Cy - By, bcz = Cz - Bz;
            float rn = 1.0f / sqrtf(bcx * bcx + bcy * bcy + bcz * bcz);
            bcx *= rn; bcy *= rn; bcz *= rn;
            float abx = Bx - Ax, aby = By - Ay, abz = Bz - Az;
            float nx = aby * bcz - abz * bcy;
            float ny = abz * bcx - abx * bcz;
            float nz = abx * bcy - aby * bcx;
            float rn2 = 1.0f / sqrtf(nx * nx + ny * ny + nz * nz);
            nx *= rn2; ny *= rn2; nz *= rn2;
            float m1x = ny * bcz - nz * bcy;
            float m1y = nz * bcx - nx * bcz;
            float m1z = nx * bcy - ny * bcx;
            float Dx = bcx * d2x + m1x * d2y + nx * d2z + Cx;
            float Dy = bcy * d2x + m1y * d2y + ny * d2z + Cy;
            float Dz = bcz * d2x + m1z * d2y + nz * d2z + Cz;
            size_t obase = ((size_t)(3 + 3 * s + i) * BATCH + b) * 3;
            out[obase + 0] = Dx; out[obase + 1] = Dy; out[obase + 2] = Dz;
            Ax = Bx; Ay = By; Az = Bz;
            Bx = Cx; By = Cy; Bz = Cz;
            Cx = Dx; Cy = Dy; Cz = Dz;
        }
    }
}

// ---------------- launch ----------------
extern "C" void kernel_launch(void* const* d_in, const int* in_sizes, int n_in,
                              void* d_out, int out_size) {
    const float* seq   = (const float*)d_in[0];
    const float* w_ih0 = (const float*)d_in[2];
    const float* w_hh0 = (const float*)d_in[3];
    const float* b0    = (const float*)d_in[4];
    const float* w_ih1 = (const float*)d_in[5];
    const float* w_hh1 = (const float*)d_in[6];
    const float* b1    = (const float*)d_in[7];
    const float* lin_w = (const float*)d_in[8];
    const float* lin_b = (const float*)d_in[9];
    const float* alpha = (const float*)d_in[10];
    float* out = (float*)d_out;

    static int smem_set = 0;
    if (!smem_set) {
        cudaFuncSetAttribute(k_lstm_mma, cudaFuncAttributeMaxDynamicSharedMemorySize,
                             LSTM_SMEM);
        smem_set = 1;
    }

    const int n_whh = 2 * G4 * HID;       // 5,120,000
    const int n_wih1 = NTOT * KTOT;       // 10,240,000

    k_xw0<<<dim3(G4 / 128, T_LEN, 2), 128>>>(seq, w_ih0, b0);
    k_cvt<<<(n_whh + 255) / 256, 256>>>(w_hh0, 1);
    k_lstm_mma<<<dim3(HID / 16, 2), 256, LSTM_SMEM>>>(0);
    k_cvt<<<(n_wih1 + 255) / 256, 256>>>(w_ih1, 0);
    k_xw1_mma<<<dim3(NTOT / 128, MTOT / 128), 256>>>(b1);
    k_cvt<<<(n_whh + 255) / 256, 256>>>(w_hh1, 1);
    k_lstm_mma<<<dim3(HID / 16, 2), 256, LSTM_SMEM>>>(1);
    k_head<<<(T_LEN * BATCH) / 8, 256>>>(lin_w, lin_b, alpha);
    k_geom<<<1, 32>>>(out);
}

// round 8
// speedup vs baseline: 3.6866x; 1.0768x over previous
#include <cuda_runtime.h>
#include <cuda_bf16.h>
#include <math.h>
#include <stdint.h>

#define T_LEN 512
#define BATCH 32
#define EMB   41
#define HID   800
#define G4    3200
#define IN0   42
#define IN1   1600
#define UNITS 20
#define MTOT  (T_LEN*BATCH)   // 16384
#define NTOT  6400
#define KTOT  1600

// ---------------- device scratch ----------------
__device__ float g_xw[2u * T_LEN * BATCH * G4];
__device__ float g_ang[MTOT * 3];
// hidden states as bf16 hi/lo splits: [m = t*32+b][1600]
__device__ __nv_bfloat16 g_h0h[(size_t)MTOT * IN1];
__device__ __nv_bfloat16 g_h0l[(size_t)MTOT * IN1];
__device__ __nv_bfloat16 g_h1h[(size_t)MTOT * IN1];
__device__ __nv_bfloat16 g_h1l[(size_t)MTOT * IN1];
// w_ih1 split
__device__ __nv_bfloat16 g_wh[(size_t)NTOT * KTOT];
__device__ __nv_bfloat16 g_wl[(size_t)NTOT * KTOT];
// w_hh splits, per layer: [d][3200][800]
__device__ __nv_bfloat16 g_whhh0[(size_t)2 * G4 * HID];
__device__ __nv_bfloat16 g_whhl0[(size_t)2 * G4 * HID];
__device__ __nv_bfloat16 g_whhh1[(size_t)2 * G4 * HID];
__device__ __nv_bfloat16 g_whhl1[(size_t)2 * G4 * HID];
__device__ unsigned g_barcnt[2];
__device__ unsigned g_bargen[2];

__device__ __forceinline__ float sigf(float x) { return 1.0f / (1.0f + __expf(-x)); }
__device__ __forceinline__ float tanhfast(float x) {
    float a = fabsf(x);
    float e = __expf(2.0f * a);
    float r = 1.0f - 2.0f / (e + 1.0f);
    return copysignf(r, x);
}
__device__ __forceinline__ uint32_t s2u(const void* p) {
    uint32_t a; asm("{.reg .u64 t; cvta.to.shared.u64 t, %1; cvt.u32.u64 %0, t;}" : "=r"(a) : "l"(p));
    return a;
}
__device__ __forceinline__ void ldsm4(uint32_t& r0, uint32_t& r1, uint32_t& r2,
                                      uint32_t& r3, uint32_t addr) {
    asm volatile("ldmatrix.sync.aligned.m8n8.x4.shared.b16 {%0,%1,%2,%3}, [%4];"
                 : "=r"(r0), "=r"(r1), "=r"(r2), "=r"(r3) : "r"(addr));
}
__device__ __forceinline__ void mma_bf16(float* c, const uint32_t* a, const uint32_t* b) {
    asm volatile("mma.sync.aligned.m16n8k16.row.col.f32.bf16.bf16.f32 "
                 "{%0,%1,%2,%3}, {%4,%5,%6,%7}, {%8,%9}, {%0,%1,%2,%3};"
                 : "+f"(c[0]), "+f"(c[1]), "+f"(c[2]), "+f"(c[3])
                 : "r"(a[0]), "r"(a[1]), "r"(a[2]), "r"(a[3]), "r"(b[0]), "r"(b[1]));
}

// ---------------- layer0 input projection ----------------
__global__ void k_xw0(const float* __restrict__ seq, const float* __restrict__ w_ih,
                      const float* __restrict__ bias) {
    __shared__ float xs[BATCH * IN0];
    int t = blockIdx.y, d = blockIdx.z;
    int g = blockIdx.x * 128 + threadIdx.x;
    for (int e = threadIdx.x; e < BATCH * IN0; e += 128) {
        int b = e / IN0, i = e % IN0;
        xs[e] = (i < EMB) ? seq[(size_t)(t * BATCH + b) * EMB + i] : (float)t;
    }
    __syncthreads();
    float acc[BATCH];
    float bv = bias[d * G4 + g];
#pragma unroll
    for (int b = 0; b < BATCH; b++) acc[b] = bv;
    const float* wrow = w_ih + (size_t)(d * G4 + g) * IN0;
#pragma unroll
    for (int i = 0; i < IN0; i++) {
        float wv = wrow[i];
#pragma unroll
        for (int b = 0; b < BATCH; b++) acc[b] += wv * xs[b * IN0 + i];
    }
    size_t base = ((size_t)(d * T_LEN + t) * BATCH) * G4 + g;
#pragma unroll
    for (int b = 0; b < BATCH; b++) g_xw[base + (size_t)b * G4] = acc[b];
}

// ---------------- bf16 split converter ----------------
// mode 0: w_ih1 -> g_wh/g_wl ; 1: w_hh0 -> whh*0 ; 2: w_hh1 -> whh*1
__global__ void k_cvt(const float* __restrict__ src, int mode) {
    size_t n = mode ? (size_t)2 * G4 * HID : (size_t)NTOT * KTOT;
    __nv_bfloat16* dh = (mode == 0) ? g_wh : (mode == 1 ? g_whhh0 : g_whhh1);
    __nv_bfloat16* dl = (mode == 0) ? g_wl : (mode == 1 ? g_whhl0 : g_whhl1);
    size_t i = (size_t)blockIdx.x * 256 + threadIdx.x;
    if (i >= n) return;
    float v = src[i];
    __nv_bfloat16 h = __float2bfloat16(v);
    dh[i] = h;
    dl[i] = __float2bfloat16(v - __bfloat162float(h));
}

// ---------------- barrier init ----------------
__global__ void k_init() {
    if (threadIdx.x < 2) { g_barcnt[threadIdx.x] = 0; g_bargen[threadIdx.x] = 0; }
}

// ---------------- persistent LSTM layer: mma.sync recurrence --------------
// grid (50, 2), 256 thr (8 warps). Block: dir=blockIdx.y, 16 hid units = 64
// gate cols. W (hi+lo) resident in smem; h_prev streamed in K-chunks of 32.
#define WH_OFF 0
#define WL_OFF 103424
#define A_OFF  206848
#define LSTM_SMEM 217088

__global__ void __launch_bounds__(256, 1)
k_lstm_mma(int layer) {
    extern __shared__ __align__(16) uint8_t sm[];
    const uint32_t sbase = s2u(sm);
    const int tid = threadIdx.x, lane = tid & 31, w = tid >> 5;
    const int d = blockIdx.y, j0 = blockIdx.x * 16;
    const int nblk = gridDim.x;

    __nv_bfloat16* hh = layer ? g_h1h : g_h0h;
    __nv_bfloat16* hl = layer ? g_h1l : g_h0l;
    const __nv_bfloat16* whhh = layer ? g_whhh1 : g_whhh0;
    const __nv_bfloat16* whhl = layer ? g_whhl1 : g_whhl0;
    float* Gt = (float*)(sm + A_OFF);   // aliases A buffers; [32][68]

    // load W slice (64 rows x 800) hi+lo into smem, padded stride 1616 B.
    for (int idx = tid; idx < 12800; idx += 256) {
        int s = idx >= 6400;
        int e = idx - s * 6400;
        int r = e / 100, c = e % 100;
        int grow = (r >> 4) * HID + j0 + (r & 15);
        const __nv_bfloat16* src = (s ? whhl : whhh)
                                 + ((size_t)(d * G4 + grow) * HID + c * 8);
        *(uint4*)(sm + (s ? WL_OFF : WH_OFF) + r * 1616 + c * 16) = *(const uint4*)src;
    }
    __syncthreads();

    // ldmatrix index decomposition
    const int lr = lane & 7, q = lane >> 3;
    const int a_row = (q & 1) * 8 + lr;       // + mt*16
    const int a_kh  = (q >> 1) * 8;           // + ks*16
    const uint32_t b_base = sbase + (uint32_t)((w * 8 + lr) * 1616 + q * 16);

    // A prefetch decomposition: 1 uint4/thread, covers both splits
    const int s0 = tid >> 7, ae = tid & 127;
    const int arow = ae >> 2, ac4 = ae & 3;

    // epilogue (b, jj) ownership (fixed per thread) -> cell state in registers
    const int eb0 = tid >> 4, ejj = tid & 15;        // q=0 pair
    const int eb1 = (tid + 256) >> 4;                // q=1 pair
    float creg[2] = {0.0f, 0.0f};

    for (int t = 0; t < T_LEN; t++) {
        const int tt = d ? (T_LEN - 1 - t) : t;
        const int tp = d ? tt + 1 : t - 1;

        // prefetch gate biases (8 scattered floats) -- hidden under MMA loop
        const size_t xwb = ((size_t)(d * T_LEN + tt) * BATCH) * G4;
        float xg[2][4];
#pragma unroll
        for (int e = 0; e < 4; e++) {
            xg[0][e] = __ldg(g_xw + xwb + (size_t)eb0 * G4 + e * HID + j0 + ejj);
            xg[1][e] = __ldg(g_xw + xwb + (size_t)eb1 * G4 + e * HID + j0 + ejj);
        }

        float acc[2][4];
#pragma unroll
        for (int mt = 0; mt < 2; mt++)
#pragma unroll
            for (int i = 0; i < 4; i++) acc[mt][i] = 0.0f;

        if (t > 0) {
            const __nv_bfloat16* asrc = (s0 ? hl : hh)
                + (size_t)(tp * BATCH + arow) * IN1 + d * HID + ac4 * 8;
            uint4 v = *(const uint4*)asrc;
            *(uint4*)(sm + A_OFF + s0 * 2560 + arow * 80 + ac4 * 16) = v;
            __syncthreads();

            for (int kc = 0; kc < 25; kc++) {
                const int cb = kc & 1;
                if (kc < 24) v = *(const uint4*)(asrc + (kc + 1) * 32);

                const uint32_t wb = b_base + (uint32_t)(kc * 64);
                uint32_t bh[4], bl[4];
                ldsm4(bh[0], bh[1], bh[2], bh[3], wb + WH_OFF);
                ldsm4(bl[0], bl[1], bl[2], bl[3], wb + WL_OFF);
#pragma unroll
                for (int ks = 0; ks < 2; ks++) {
#pragma unroll
                    for (int mt = 0; mt < 2; mt++) {
                        uint32_t ah[4], al[4];
                        uint32_t aa = sbase + A_OFF + cb * 5120
                                    + (uint32_t)((mt * 16 + a_row) * 80
                                    + (ks * 16 + a_kh) * 2);
                        ldsm4(ah[0], ah[1], ah[2], ah[3], aa);
                        ldsm4(al[0], al[1], al[2], al[3], aa + 2560);
                        mma_bf16(acc[mt], ah, &bh[ks * 2]);
                        mma_bf16(acc[mt], ah, &bl[ks * 2]);
                        mma_bf16(acc[mt], al, &bh[ks * 2]);
                    }
                }
                if (kc < 24)
                    *(uint4*)(sm + A_OFF + (cb ^ 1) * 5120 + s0 * 2560
                              + arow * 80 + ac4 * 16) = v;
                __syncthreads();
            }
        }

        // stage gates into smem (Gt aliases A buffers; safe after last sync)
#pragma unroll
        for (int mt = 0; mt < 2; mt++) {
            int r = mt * 16 + (lane >> 2);
            int c = w * 8 + (lane & 3) * 2;
            Gt[r * 68 + c]           = acc[mt][0];
            Gt[r * 68 + c + 1]       = acc[mt][1];
            Gt[(r + 8) * 68 + c]     = acc[mt][2];
            Gt[(r + 8) * 68 + c + 1] = acc[mt][3];
        }
        __syncthreads();

        // pointwise epilogue: 512 (b, j) pairs / 256 threads, c in registers
#pragma unroll
        for (int qq = 0; qq < 2; qq++) {
            int b = qq ? eb1 : eb0;
            float g0 = Gt[b * 68 + ejj]      + xg[qq][0];
            float g1 = Gt[b * 68 + 16 + ejj] + xg[qq][1];
            float g2 = Gt[b * 68 + 32 + ejj] + xg[qq][2];
            float g3 = Gt[b * 68 + 48 + ejj] + xg[qq][3];
            float cold = (t > 0) ? creg[qq] : 0.0f;
            float cn = sigf(g1) * cold + sigf(g0) * tanhfast(g2);
            float hn = sigf(g3) * tanhfast(cn);
            creg[qq] = cn;
            size_t ho = (size_t)(tt * BATCH + b) * IN1 + d * HID + j0 + ejj;
            __nv_bfloat16 hhi = __float2bfloat16(hn);
            hh[ho] = hhi;
            hl[ho] = __float2bfloat16(hn - __bfloat162float(hhi));
        }

        // per-direction grid barrier (skip after last step)
        if (t + 1 < T_LEN) {
            __threadfence();
            __syncthreads();
            if (tid == 0) {
                volatile unsigned* vg = (volatile unsigned*)&g_bargen[d];
                unsigned gen = *vg;
                unsigned arrived = atomicAdd(&g_barcnt[d], 1u);
                if (arrived == (unsigned)(nblk - 1)) {
                    g_barcnt[d] = 0;
                    __threadfence();
                    atomicExch(&g_bargen[d], gen + 1u);
                } else {
                    while (*vg == gen) { }
                }
            }
            __syncthreads();
        }
    }
}

// ---------------- xw1: mma.sync bf16-split GEMM ----------------
__global__ void __launch_bounds__(256)
k_xw1_mma(const float* __restrict__ bias) {
    __shared__ __align__(1024) uint8_t sm[2 * 16384];
    const uint32_t sbase = s2u(sm);

    const int tid = threadIdx.x;
    const int lane = tid & 31, wid = tid >> 5;
    const int wm = wid >> 2, wn = wid & 3;
    const int lm = lane >> 3, lr = lane & 7;
    const int n0 = blockIdx.x * 128, m0 = blockIdx.y * 128;

    const int a_row_b = wm * 64 + (lm & 1) * 8 + lr;
    const int a_c_b   = (lm >> 1);
    const int b_row_b = wn * 32 + (lm >> 1) * 8 + lr;
    const int b_c_b   = (lm & 1);

    float acc[4][4][4];
#pragma unroll
    for (int i = 0; i < 4; i++)
#pragma unroll
        for (int j = 0; j < 4; j++)
#pragma unroll
            for (int q = 0; q < 4; q++) acc[i][j][q] = 0.0f;

    const int f_row0 = tid >> 2, f_c0 = tid & 3;
    const int f_row1 = (tid + 256) >> 2, f_c1 = tid & 3;
    const int f_sc0 = f_c0 ^ ((f_row0 >> 1) & 3);
    const int f_sc1 = f_c1 ^ ((f_row1 >> 1) & 3);

    {
        const __nv_bfloat16* pa = g_h0h + (size_t)m0 * KTOT;
        const __nv_bfloat16* pb = g_wh + (size_t)n0 * KTOT;
        *(uint4*)(sm + f_row0 * 64 + f_sc0 * 16) = *(const uint4*)(pa + (size_t)f_row0 * KTOT + f_c0 * 8);
        *(uint4*)(sm + f_row1 * 64 + f_sc1 * 16) = *(const uint4*)(pa + (size_t)f_row1 * KTOT + f_c1 * 8);
        *(uint4*)(sm + 8192 + f_row0 * 64 + f_sc0 * 16) = *(const uint4*)(pb + (size_t)f_row0 * KTOT + f_c0 * 8);
        *(uint4*)(sm + 8192 + f_row1 * 64 + f_sc1 * 16) = *(const uint4*)(pb + (size_t)f_row1 * KTOT + f_c1 * 8);
    }
    __syncthreads();

    for (int it = 0; it < 150; it++) {
        const int cur = it & 1;
        uint4 ra0, ra1, rb0, rb1;
        if (it + 1 < 150) {
            const int nit = it + 1;
            const int pass = nit / 50, kt = nit - pass * 50;
            const int koff = kt * 32;
            const __nv_bfloat16* pa = (pass == 2 ? g_h0l : g_h0h) + (size_t)m0 * KTOT + koff;
            const __nv_bfloat16* pb = (pass == 1 ? g_wl : g_wh) + (size_t)n0 * KTOT + koff;
            ra0 = *(const uint4*)(pa + (size_t)f_row0 * KTOT + f_c0 * 8);
            ra1 = *(const uint4*)(pa + (size_t)f_row1 * KTOT + f_c1 * 8);
            rb0 = *(const uint4*)(pb + (size_t)f_row0 * KTOT + f_c0 * 8);
            rb1 = *(const uint4*)(pb + (size_t)f_row1 * KTOT + f_c1 * 8);
        }

        const uint32_t abase = sbase + cur * 16384;
        const uint32_t bbase = abase + 8192;
#pragma unroll
        for (int ks = 0; ks < 2; ks++) {
            uint32_t af[4][4], bf[4][2];
#pragma unroll
            for (int i = 0; i < 4; i++) {
                int row = a_row_b + i * 16;
                int c = (2 * ks + a_c_b) ^ ((row >> 1) & 3);
                ldsm4(af[i][0], af[i][1], af[i][2], af[i][3], abase + row * 64 + c * 16);
            }
#pragma unroll
            for (int p = 0; p < 2; p++) {
                int row = b_row_b + p * 16;
                int c = (2 * ks + b_c_b) ^ ((row >> 1) & 3);
                ldsm4(bf[p * 2][0], bf[p * 2][1], bf[p * 2 + 1][0], bf[p * 2 + 1][1],
                      bbase + row * 64 + c * 16);
            }
#pragma unroll
            for (int i = 0; i < 4; i++)
#pragma unroll
                for (int j = 0; j < 4; j++) mma_bf16(acc[i][j], af[i], bf[j]);
        }

        if (it + 1 < 150) {
            uint8_t* dst = sm + ((it + 1) & 1) * 16384;
            *(uint4*)(dst + f_row0 * 64 + f_sc0 * 16) = ra0;
            *(uint4*)(dst + f_row1 * 64 + f_sc1 * 16) = ra1;
            *(uint4*)(dst + 8192 + f_row0 * 64 + f_sc0 * 16) = rb0;
            *(uint4*)(dst + 8192 + f_row1 * 64 + f_sc1 * 16) = rb1;
        }
        __syncthreads();
    }

    const int dd = n0 / G4;
    const size_t dbase = (size_t)dd * ((size_t)MTOT * G4);
#pragma unroll
    for (int i = 0; i < 4; i++) {
        int mrow = m0 + wm * 64 + i * 16 + (lane >> 2);
#pragma unroll
        for (int j = 0; j < 4; j++) {
            int n = n0 + wn * 32 + j * 8 + (lane & 3) * 2;
            int gc = n - dd * G4;
            float2 bv = *(const float2*)(bias + n);
            float2 o0 = { acc[i][j][0] + bv.x, acc[i][j][1] + bv.y };
            float2 o1 = { acc[i][j][2] + bv.x, acc[i][j][3] + bv.y };
            *(float2*)(g_xw + dbase + (size_t)mrow * G4 + gc) = o0;
            *(float2*)(g_xw + dbase + (size_t)(mrow + 8) * G4 + gc) = o1;
        }
    }
}

// ---------------- head ----------------
__global__ void k_head(const float* __restrict__ lin_w, const float* __restrict__ lin_b,
                       const float* __restrict__ alpha) {
    __shared__ float sl[8][UNITS];
    int warp = threadIdx.x >> 5, lane = threadIdx.x & 31;
    int m = blockIdx.x * 8 + warp;
    const __nv_bfloat16* hrh = g_h1h + (size_t)m * IN1;
    const __nv_bfloat16* hrl = g_h1l + (size_t)m * IN1;
    for (int u = 0; u < UNITS; u++) {
        float s = 0.0f;
        const float* wrow = lin_w + (size_t)u * IN1;
        for (int i = lane; i < IN1; i += 32)
            s += (__bfloat162float(hrh[i]) + __bfloat162float(hrl[i])) * wrow[i];
#pragma unroll
        for (int off = 16; off; off >>= 1) s += __shfl_xor_sync(0xffffffffu, s, off);
        if (lane == 0) sl[warp][u] = s + lin_b[u];
    }
    __syncwarp();
    float v = (lane < UNITS) ? sl[warp][lane] : -INFINITY;
    float mx = v;
#pragma unroll
    for (int off = 16; off; off >>= 1) mx = fmaxf(mx, __shfl_xor_sync(0xffffffffu, mx, off));
    float e = (lane < UNITS) ? expf(v - mx) : 0.0f;
    float se = e;
#pragma unroll
    for (int off = 16; off; off >>= 1) se += __shfl_xor_sync(0xffffffffu, se, off);
    float soft = e / se;
#pragma unroll
    for (int j = 0; j < 3; j++) {
        float a = (lane < UNITS) ? alpha[lane * 3 + j] : 0.0f;
        float ss = soft * sinf(a), cc = soft * cosf(a);
#pragma unroll
        for (int off = 16; off; off >>= 1) {
            ss += __shfl_xor_sync(0xffffffffu, ss, off);
            cc += __shfl_xor_sync(0xffffffffu, cc, off);
        }
        if (lane == 0) g_ang[(size_t)m * 3 + j] = atan2f(ss, cc);
    }
}

// ---------------- geometric chain ----------------
__global__ void k_geom(float* __restrict__ out) {
    int b = threadIdx.x;
    if (b >= BATCH) return;
    const float RL[3] = {1.329f, 1.459f, 1.525f};
    const float TA[3] = {2.034f, 2.119f, 1.937f};
    float cT[3], sT[3];
#pragma unroll
    for (int i = 0; i < 3; i++) { cT[i] = cosf(TA[i]); sT[i] = sinf(TA[i]); }
    float Ax = 0.f, Ay = 0.f, Az = 1.f;
    float Bx = 0.f, By = 1.f, Bz = 0.f;
    float Cx = 1.f, Cy = 0.f, Cz = 0.f;
    out[(0 * BATCH + b) * 3 + 0] = Ax; out[(0 * BATCH + b) * 3 + 1] = Ay; out[(0 * BATCH + b) * 3 + 2] = Az;
    out[(1 * BATCH + b) * 3 + 0] = Bx; out[(1 * BATCH + b) * 3 + 1] = By; out[(1 * BATCH + b) * 3 + 2] = Bz;
    out[(2 * BATCH + b) * 3 + 0] = Cx; out[(2 * BATCH + b) * 3 + 1] = Cy; out[(2 * BATCH + b) * 3 + 2] = Cz;
    for (int s = 0; s < T_LEN - 1; s++) {
        size_t abase = ((size_t)(s + 1) * BATCH + b) * 3;
#pragma unroll
        for (int i = 0; i < 3; i++) {
            float P = g_ang[abase + i];
            float d2x = -RL[i] * cT[i];
            float d2y = RL[i] * cosf(P) * sT[i];
            float d2z = RL[i] * sinf(P) * sT[i];
            float bcx = Cx - Bx, bcy = Cy - By, bcz = Cz - Bz;
            float rn = 1.0f / sqrtf(bcx * bcx + bcy * bcy + bcz * bcz);
            bcx *= rn; bcy *= rn; bcz *= rn;
            float abx = Bx - Ax, aby = By - Ay, abz = Bz - Az;
            float nx = aby * bcz - abz * bcy;
            float ny = abz * bcx - abx * bcz;
            float nz = abx * bcy - aby * bcx;
            float rn2 = 1.0f / sqrtf(nx * nx + ny * ny + nz * nz);
            nx *= rn2; ny *= rn2; nz *= rn2;
            float m1x = ny * bcz - nz * bcy;
            float m1y = nz * bcx - nx * bcz;
            float m1z = nx * bcy - ny * bcx;
            float Dx = bcx * d2x + m1x * d2y + nx * d2z + Cx;
            float Dy = bcy * d2x + m1y * d2y + ny * d2z + Cy;
            float Dz = bcz * d2x + m1z * d2y + nz * d2z + Cz;
            size_t obase = ((size_t)(3 + 3 * s + i) * BATCH + b) * 3;
            out[obase + 0] = Dx; out[obase + 1] = Dy; out[obase + 2] = Dz;
            Ax = Bx; Ay = By; Az = Bz;
            Bx = Cx; By = Cy; Bz = Cz;
            Cx = Dx; Cy = Dy; Cz = Dz;
        }
    }
}

// ---------------- launch ----------------
extern "C" void kernel_launch(void* const* d_in, const int* in_sizes, int n_in,
                              void* d_out, int out_size) {
    const float* seq   = (const float*)d_in[0];
    const float* w_ih0 = (const float*)d_in[2];
    const float* w_hh0 = (const float*)d_in[3];
    const float* b0    = (const float*)d_in[4];
    const float* w_ih1 = (const float*)d_in[5];
    const float* w_hh1 = (const float*)d_in[6];
    const float* b1    = (const float*)d_in[7];
    const float* lin_w = (const float*)d_in[8];
    const float* lin_b = (const float*)d_in[9];
    const float* alpha = (const float*)d_in[10];
    float* out = (float*)d_out;

    static int smem_set = 0;
    if (!smem_set) {
        cudaFuncSetAttribute(k_lstm_mma, cudaFuncAttributeMaxDynamicSharedMemorySize,
                             LSTM_SMEM);
        smem_set = 1;
    }

    const int n_whh = 2 * G4 * HID;       // 5,120,000
    const int n_wih1 = NTOT * KTOT;       // 10,240,000

    // launch order arranged so ncu (-s 5 -c 1) captures k_lstm_mma(0) [#6]
    k_xw0<<<dim3(G4 / 128, T_LEN, 2), 128>>>(seq, w_ih0, b0);         // 1
    k_cvt<<<(n_whh + 255) / 256, 256>>>(w_hh0, 1);                    // 2
    k_cvt<<<(n_whh + 255) / 256, 256>>>(w_hh1, 2);                    // 3
    k_cvt<<<(n_wih1 + 255) / 256, 256>>>(w_ih1, 0);                   // 4
    k_init<<<1, 32>>>();                                              // 5
    k_lstm_mma<<<dim3(HID / 16, 2), 256, LSTM_SMEM>>>(0);             // 6 <- profiled
    k_xw1_mma<<<dim3(NTOT / 128, MTOT / 128), 256>>>(b1);             // 7
    k_lstm_mma<<<dim3(HID / 16, 2), 256, LSTM_SMEM>>>(1);             // 8
    k_head<<<(T_LEN * BATCH) / 8, 256>>>(lin_w, lin_b, alpha);        // 9
    k_geom<<<1, 32>>>(out);                                           // 10
}

// round 9
// speedup vs baseline: 4.0605x; 1.1014x over previous
#include <cuda_runtime.h>
#include <cuda_bf16.h>
#include <math.h>
#include <stdint.h>

#define T_LEN 512
#define BATCH 32
#define EMB   41
#define HID   800
#define G4    3200
#define IN0   42
#define IN1   1600
#define UNITS 20
#define MTOT  (T_LEN*BATCH)   // 16384
#define NTOT  6400
#define KTOT  1600

// ---------------- device scratch ----------------
__device__ float g_xw[2u * T_LEN * BATCH * G4];
__device__ float g_ang[MTOT * 3];
__device__ __nv_bfloat16 g_h0h[(size_t)MTOT * IN1];
__device__ __nv_bfloat16 g_h0l[(size_t)MTOT * IN1];
__device__ __nv_bfloat16 g_h1h[(size_t)MTOT * IN1];
__device__ __nv_bfloat16 g_h1l[(size_t)MTOT * IN1];
__device__ __nv_bfloat16 g_wh[(size_t)NTOT * KTOT];
__device__ __nv_bfloat16 g_wl[(size_t)NTOT * KTOT];
__device__ __nv_bfloat16 g_whhh0[(size_t)2 * G4 * HID];
__device__ __nv_bfloat16 g_whhl0[(size_t)2 * G4 * HID];
__device__ __nv_bfloat16 g_whhh1[(size_t)2 * G4 * HID];
__device__ __nv_bfloat16 g_whhl1[(size_t)2 * G4 * HID];
__device__ unsigned g_barcnt[2];
__device__ unsigned g_bargen[2];

__device__ __forceinline__ float sigf(float x) { return 1.0f / (1.0f + __expf(-x)); }
__device__ __forceinline__ float tanhfast(float x) {
    float a = fabsf(x);
    float e = __expf(2.0f * a);
    float r = 1.0f - 2.0f / (e + 1.0f);
    return copysignf(r, x);
}
__device__ __forceinline__ uint32_t s2u(const void* p) {
    uint32_t a; asm("{.reg .u64 t; cvta.to.shared.u64 t, %1; cvt.u32.u64 %0, t;}" : "=r"(a) : "l"(p));
    return a;
}
__device__ __forceinline__ void ldsm4(uint32_t& r0, uint32_t& r1, uint32_t& r2,
                                      uint32_t& r3, uint32_t addr) {
    asm volatile("ldmatrix.sync.aligned.m8n8.x4.shared.b16 {%0,%1,%2,%3}, [%4];"
                 : "=r"(r0), "=r"(r1), "=r"(r2), "=r"(r3) : "r"(addr));
}
__device__ __forceinline__ void mma_bf16(float* c, const uint32_t* a, const uint32_t* b) {
    asm volatile("mma.sync.aligned.m16n8k16.row.col.f32.bf16.bf16.f32 "
                 "{%0,%1,%2,%3}, {%4,%5,%6,%7}, {%8,%9}, {%0,%1,%2,%3};"
                 : "+f"(c[0]), "+f"(c[1]), "+f"(c[2]), "+f"(c[3])
                 : "r"(a[0]), "r"(a[1]), "r"(a[2]), "r"(a[3]), "r"(b[0]), "r"(b[1]));
}
__device__ __forceinline__ unsigned atom_add_acqrel(unsigned* p) {
    unsigned old;
    asm volatile("atom.add.acq_rel.gpu.u32 %0, [%1], 1;" : "=r"(old) : "l"(p) : "memory");
    return old;
}
__device__ __forceinline__ unsigned ld_acq(unsigned* p) {
    unsigned v;
    asm volatile("ld.acquire.gpu.u32 %0, [%1];" : "=r"(v) : "l"(p) : "memory");
    return v;
}
__device__ __forceinline__ void st_rel(unsigned* p, unsigned v) {
    asm volatile("st.release.gpu.u32 [%0], %1;" :: "l"(p), "r"(v) : "memory");
}

// ---------------- layer0 input projection ----------------
__global__ void k_xw0(const float* __restrict__ seq, const float* __restrict__ w_ih,
                      const float* __restrict__ bias) {
    __shared__ float xs[BATCH * IN0];
    int t = blockIdx.y, d = blockIdx.z;
    int g = blockIdx.x * 128 + threadIdx.x;
    for (int e = threadIdx.x; e < BATCH * IN0; e += 128) {
        int b = e / IN0, i = e % IN0;
        xs[e] = (i < EMB) ? seq[(size_t)(t * BATCH + b) * EMB + i] : (float)t;
    }
    __syncthreads();
    float acc[BATCH];
    float bv = bias[d * G4 + g];
#pragma unroll
    for (int b = 0; b < BATCH; b++) acc[b] = bv;
    const float* wrow = w_ih + (size_t)(d * G4 + g) * IN0;
#pragma unroll
    for (int i = 0; i < IN0; i++) {
        float wv = wrow[i];
#pragma unroll
        for (int b = 0; b < BATCH; b++) acc[b] += wv * xs[b * IN0 + i];
    }
    size_t base = ((size_t)(d * T_LEN + t) * BATCH) * G4 + g;
#pragma unroll
    for (int b = 0; b < BATCH; b++) g_xw[base + (size_t)b * G4] = acc[b];
}

// ---------------- bf16 split converter ----------------
__global__ void k_cvt(const float* __restrict__ src, int mode) {
    size_t n = mode ? (size_t)2 * G4 * HID : (size_t)NTOT * KTOT;
    __nv_bfloat16* dh = (mode == 0) ? g_wh : (mode == 1 ? g_whhh0 : g_whhh1);
    __nv_bfloat16* dl = (mode == 0) ? g_wl : (mode == 1 ? g_whhl0 : g_whhl1);
    size_t i = (size_t)blockIdx.x * 256 + threadIdx.x;
    if (i >= n) return;
    float v = src[i];
    __nv_bfloat16 h = __float2bfloat16(v);
    dh[i] = h;
    dl[i] = __float2bfloat16(v - __bfloat162float(h));
}

// ---------------- barrier init ----------------
__global__ void k_init() {
    if (threadIdx.x < 2) { g_barcnt[threadIdx.x] = 0; g_bargen[threadIdx.x] = 0; }
}

// ---------------- persistent LSTM layer: mma.sync recurrence --------------
// grid (50, 2), 256 thr. W (hi+lo) smem-resident; A streamed through a
// 4-buffer smem pipe with a 3-deep register window (fully unrolled).
#define WH_OFF 0
#define WL_OFF 103424
#define A_OFF  206848
#define LSTM_SMEM 227328

__global__ void __launch_bounds__(256, 1)
k_lstm_mma(int layer) {
    extern __shared__ __align__(16) uint8_t sm[];
    const uint32_t sbase = s2u(sm);
    const int tid = threadIdx.x, lane = tid & 31, w = tid >> 5;
    const int d = blockIdx.y, j0 = blockIdx.x * 16;
    const int nblk = gridDim.x;

    __nv_bfloat16* hh = layer ? g_h1h : g_h0h;
    __nv_bfloat16* hl = layer ? g_h1l : g_h0l;
    const __nv_bfloat16* whhh = layer ? g_whhh1 : g_whhh0;
    const __nv_bfloat16* whhl = layer ? g_whhl1 : g_whhl0;
    float* Gt = (float*)(sm + A_OFF);   // aliases A buffers; [32][68]

    for (int idx = tid; idx < 12800; idx += 256) {
        int s = idx >= 6400;
        int e = idx - s * 6400;
        int r = e / 100, c = e % 100;
        int grow = (r >> 4) * HID + j0 + (r & 15);
        const __nv_bfloat16* src = (s ? whhl : whhh)
                                 + ((size_t)(d * G4 + grow) * HID + c * 8);
        *(uint4*)(sm + (s ? WL_OFF : WH_OFF) + r * 1616 + c * 16) = *(const uint4*)src;
    }
    __syncthreads();

    const int lr = lane & 7, q = lane >> 3;
    const int a_row = (q & 1) * 8 + lr;
    const int a_kh  = (q >> 1) * 8;
    const uint32_t b_base = sbase + (uint32_t)((w * 8 + lr) * 1616 + q * 16);

    // A staging decomposition: 1 uint4/thread per chunk (both splits)
    const int s0 = tid >> 7, ae = tid & 127;
    const int arow = ae >> 2, ac4 = ae & 3;
    const uint32_t a_st_off = (uint32_t)(s0 * 2560 + arow * 80 + ac4 * 16);

    const int eb0 = tid >> 4, ejj = tid & 15;
    const int eb1 = (tid + 256) >> 4;
    float creg[2] = {0.0f, 0.0f};

    for (int t = 0; t < T_LEN; t++) {
        const int tt = d ? (T_LEN - 1 - t) : t;
        const int tp = d ? tt + 1 : t - 1;

        const size_t xwb = ((size_t)(d * T_LEN + tt) * BATCH) * G4;
        float xg[2][4];
#pragma unroll
        for (int e = 0; e < 4; e++) {
            xg[0][e] = __ldg(g_xw + xwb + (size_t)eb0 * G4 + e * HID + j0 + ejj);
            xg[1][e] = __ldg(g_xw + xwb + (size_t)eb1 * G4 + e * HID + j0 + ejj);
        }

        float acc[2][4];
#pragma unroll
        for (int mt = 0; mt < 2; mt++)
#pragma unroll
            for (int i = 0; i < 4; i++) acc[mt][i] = 0.0f;

        if (t > 0) {
            const __nv_bfloat16* asrc = (s0 ? hl : hh)
                + (size_t)(tp * BATCH + arow) * IN1 + d * HID + ac4 * 8;

            // register window of 3 in-flight chunks
            uint4 rwin[3];
            rwin[0] = *(const uint4*)asrc;                // chunk 0
            rwin[1] = *(const uint4*)(asrc + 32);         // chunk 1
            rwin[2] = *(const uint4*)(asrc + 64);         // chunk 2
            *(uint4*)(sm + A_OFF + 0 * 5120 + a_st_off) = rwin[0];
            __syncthreads();

#pragma unroll
            for (int kc = 0; kc < 25; kc++) {
                // issue load for chunk kc+3 (lands in slot kc%3, free now)
                if (kc + 3 < 25)
                    rwin[kc % 3] = *(const uint4*)(asrc + (kc + 3) * 32);

                // compute on chunk kc (buffer kc&3)
                const uint32_t wb = b_base + (uint32_t)(kc * 64);
                uint32_t bh[4], bl[4];
                ldsm4(bh[0], bh[1], bh[2], bh[3], wb + WH_OFF);
                ldsm4(bl[0], bl[1], bl[2], bl[3], wb + WL_OFF);
#pragma unroll
                for (int ks = 0; ks < 2; ks++) {
#pragma unroll
                    for (int mt = 0; mt < 2; mt++) {
                        uint32_t ah[4], al[4];
                        uint32_t aa = sbase + A_OFF + (kc & 3) * 5120
                                    + (uint32_t)((mt * 16 + a_row) * 80
                                    + (ks * 16 + a_kh) * 2);
                        ldsm4(ah[0], ah[1], ah[2], ah[3], aa);
                        ldsm4(al[0], al[1], al[2], al[3], aa + 2560);
                        mma_bf16(acc[mt], ah, &bh[ks * 2]);
                        mma_bf16(acc[mt], ah, &bl[ks * 2]);
                        mma_bf16(acc[mt], al, &bh[ks * 2]);
                    }
                }

                // store chunk kc+1 (loaded >=2 iters ago) into buffer (kc+1)&3
                if (kc + 1 < 25)
                    *(uint4*)(sm + A_OFF + ((kc + 1) & 3) * 5120 + a_st_off)
                        = rwin[(kc + 1) % 3];
                __syncthreads();
            }
        }

        // stage gates into smem (aliases A buffers; all A reads done)
#pragma unroll
        for (int mt = 0; mt < 2; mt++) {
            int r = mt * 16 + (lane >> 2);
            int c = w * 8 + (lane & 3) * 2;
            Gt[r * 68 + c]           = acc[mt][0];
            Gt[r * 68 + c + 1]       = acc[mt][1];
            Gt[(r + 8) * 68 + c]     = acc[mt][2];
            Gt[(r + 8) * 68 + c + 1] = acc[mt][3];
        }
        __syncthreads();

#pragma unroll
        for (int qq = 0; qq < 2; qq++) {
            int b = qq ? eb1 : eb0;
            float g0 = Gt[b * 68 + ejj]      + xg[qq][0];
            float g1 = Gt[b * 68 + 16 + ejj] + xg[qq][1];
            float g2 = Gt[b * 68 + 32 + ejj] + xg[qq][2];
            float g3 = Gt[b * 68 + 48 + ejj] + xg[qq][3];
            float cold = (t > 0) ? creg[qq] : 0.0f;
            float cn = sigf(g1) * cold + sigf(g0) * tanhfast(g2);
            float hn = sigf(g3) * tanhfast(cn);
            creg[qq] = cn;
            size_t ho = (size_t)(tt * BATCH + b) * IN1 + d * HID + j0 + ejj;
            __nv_bfloat16 hhi = __float2bfloat16(hn);
            hh[ho] = hhi;
            hl[ho] = __float2bfloat16(hn - __bfloat162float(hhi));
        }

        // per-direction grid barrier: acq_rel arrive + release/acquire gen
        if (t + 1 < T_LEN) {
            __syncthreads();
            if (tid == 0) {
                unsigned gen = ld_acq(&g_bargen[d]);
                unsigned old = atom_add_acqrel(&g_barcnt[d]);
                if (old == (unsigned)(nblk - 1)) {
                    g_barcnt[d] = 0;
                    st_rel(&g_bargen[d], gen + 1u);
                } else {
                    while (ld_acq(&g_bargen[d]) == gen) { }
                }
            }
            __syncthreads();
        }
    }
}

// ---------------- xw1: mma.sync bf16-split GEMM ----------------
__global__ void __launch_bounds__(256)
k_xw1_mma(const float* __restrict__ bias) {
    __shared__ __align__(1024) uint8_t sm[2 * 16384];
    const uint32_t sbase = s2u(sm);

    const int tid = threadIdx.x;
    const int lane = tid & 31, wid = tid >> 5;
    const int wm = wid >> 2, wn = wid & 3;
    const int lm = lane >> 3, lr = lane & 7;
    const int n0 = blockIdx.x * 128, m0 = blockIdx.y * 128;

    const int a_row_b = wm * 64 + (lm & 1) * 8 + lr;
    const int a_c_b   = (lm >> 1);
    const int b_row_b = wn * 32 + (lm >> 1) * 8 + lr;
    const int b_c_b   = (lm & 1);

    float acc[4][4][4];
#pragma unroll
    for (int i = 0; i < 4; i++)
#pragma unroll
        for (int j = 0; j < 4; j++)
#pragma unroll
            for (int q = 0; q < 4; q++) acc[i][j][q] = 0.0f;

    const int f_row0 = tid >> 2, f_c0 = tid & 3;
    const int f_row1 = (tid + 256) >> 2, f_c1 = tid & 3;
    const int f_sc0 = f_c0 ^ ((f_row0 >> 1) & 3);
    const int f_sc1 = f_c1 ^ ((f_row1 >> 1) & 3);

    {
        const __nv_bfloat16* pa = g_h0h + (size_t)m0 * KTOT;
        const __nv_bfloat16* pb = g_wh + (size_t)n0 * KTOT;
        *(uint4*)(sm + f_row0 * 64 + f_sc0 * 16) = *(const uint4*)(pa + (size_t)f_row0 * KTOT + f_c0 * 8);
        *(uint4*)(sm + f_row1 * 64 + f_sc1 * 16) = *(const uint4*)(pa + (size_t)f_row1 * KTOT + f_c1 * 8);
        *(uint4*)(sm + 8192 + f_row0 * 64 + f_sc0 * 16) = *(const uint4*)(pb + (size_t)f_row0 * KTOT + f_c0 * 8);
        *(uint4*)(sm + 8192 + f_row1 * 64 + f_sc1 * 16) = *(const uint4*)(pb + (size_t)f_row1 * KTOT + f_c1 * 8);
    }
    __syncthreads();

    for (int it = 0; it < 150; it++) {
        const int cur = it & 1;
        uint4 ra0, ra1, rb0, rb1;
        if (it + 1 < 150) {
            const int nit = it + 1;
            const int pass = nit / 50, kt = nit - pass * 50;
            const int koff = kt * 32;
            const __nv_bfloat16* pa = (pass == 2 ? g_h0l : g_h0h) + (size_t)m0 * KTOT + koff;
            const __nv_bfloat16* pb = (pass == 1 ? g_wl : g_wh) + (size_t)n0 * KTOT + koff;
            ra0 = *(const uint4*)(pa + (size_t)f_row0 * KTOT + f_c0 * 8);
            ra1 = *(const uint4*)(pa + (size_t)f_row1 * KTOT + f_c1 * 8);
            rb0 = *(const uint4*)(pb + (size_t)f_row0 * KTOT + f_c0 * 8);
            rb1 = *(const uint4*)(pb + (size_t)f_row1 * KTOT + f_c1 * 8);
        }

        const uint32_t abase = sbase + cur * 16384;
        const uint32_t bbase = abase + 8192;
#pragma unroll
        for (int ks = 0; ks < 2; ks++) {
            uint32_t af[4][4], bf[4][2];
#pragma unroll
            for (int i = 0; i < 4; i++) {
                int row = a_row_b + i * 16;
                int c = (2 * ks + a_c_b) ^ ((row >> 1) & 3);
                ldsm4(af[i][0], af[i][1], af[i][2], af[i][3], abase + row * 64 + c * 16);
            }
#pragma unroll
            for (int p = 0; p < 2; p++) {
                int row = b_row_b + p * 16;
                int c = (2 * ks + b_c_b) ^ ((row >> 1) & 3);
                ldsm4(bf[p * 2][0], bf[p * 2][1], bf[p * 2 + 1][0], bf[p * 2 + 1][1],
                      bbase + row * 64 + c * 16);
            }
#pragma unroll
            for (int i = 0; i < 4; i++)
#pragma unroll
                for (int j = 0; j < 4; j++) mma_bf16(acc[i][j], af[i], bf[j]);
        }

        if (it + 1 < 150) {
            uint8_t* dst = sm + ((it + 1) & 1) * 16384;
            *(uint4*)(dst + f_row0 * 64 + f_sc0 * 16) = ra0;
            *(uint4*)(dst + f_row1 * 64 + f_sc1 * 16) = ra1;
            *(uint4*)(dst + 8192 + f_row0 * 64 + f_sc0 * 16) = rb0;
            *(uint4*)(dst + 8192 + f_row1 * 64 + f_sc1 * 16) = rb1;
        }
        __syncthreads();
    }

    const int dd = n0 / G4;
    const size_t dbase = (size_t)dd * ((size_t)MTOT * G4);
#pragma unroll
    for (int i = 0; i < 4; i++) {
        int mrow = m0 + wm * 64 + i * 16 + (lane >> 2);
#pragma unroll
        for (int j = 0; j < 4; j++) {
            int n = n0 + wn * 32 + j * 8 + (lane & 3) * 2;
            int gc = n - dd * G4;
            float2 bv = *(const float2*)(bias + n);
            float2 o0 = { acc[i][j][0] + bv.x, acc[i][j][1] + bv.y };
            float2 o1 = { acc[i][j][2] + bv.x, acc[i][j][3] + bv.y };
            *(float2*)(g_xw + dbase + (size_t)mrow * G4 + gc) = o0;
            *(float2*)(g_xw + dbase + (size_t)(mrow + 8) * G4 + gc) = o1;
        }
    }
}

// ---------------- head ----------------
__global__ void k_head(const float* __restrict__ lin_w, const float* __restrict__ lin_b,
                       const float* __restrict__ alpha) {
    __shared__ float sl[8][UNITS];
    int warp = threadIdx.x >> 5, lane = threadIdx.x & 31;
    int m = blockIdx.x * 8 + warp;
    const __nv_bfloat16* hrh = g_h1h + (size_t)m * IN1;
    const __nv_bfloat16* hrl = g_h1l + (size_t)m * IN1;
    for (int u = 0; u < UNITS; u++) {
        float s = 0.0f;
        const float* wrow = lin_w + (size_t)u * IN1;
        for (int i = lane; i < IN1; i += 32)
            s += (__bfloat162float(hrh[i]) + __bfloat162float(hrl[i])) * wrow[i];
#pragma unroll
        for (int off = 16; off; off >>= 1) s += __shfl_xor_sync(0xffffffffu, s, off);
        if (lane == 0) sl[warp][u] = s + lin_b[u];
    }
    __syncwarp();
    float v = (lane < UNITS) ? sl[warp][lane] : -INFINITY;
    float mx = v;
#pragma unroll
    for (int off = 16; off; off >>= 1) mx = fmaxf(mx, __shfl_xor_sync(0xffffffffu, mx, off));
    float e = (lane < UNITS) ? expf(v - mx) : 0.0f;
    float se = e;
#pragma unroll
    for (int off = 16; off; off >>= 1) se += __shfl_xor_sync(0xffffffffu, se, off);
    float soft = e / se;
#pragma unroll
    for (int j = 0; j < 3; j++) {
        float a = (lane < UNITS) ? alpha[lane * 3 + j] : 0.0f;
        float ss = soft * sinf(a), cc = soft * cosf(a);
#pragma unroll
        for (int off = 16; off; off >>= 1) {
            ss += __shfl_xor_sync(0xffffffffu, ss, off);
            cc += __shfl_xor_sync(0xffffffffu, cc, off);
        }
        if (lane == 0) g_ang[(size_t)m * 3 + j] = atan2f(ss, cc);
    }
}

// ---------------- geometric chain ----------------
__global__ void k_geom(float* __restrict__ out) {
    int b = threadIdx.x;
    if (b >= BATCH) return;
    const float RL[3] = {1.329f, 1.459f, 1.525f};
    const float TA[3] = {2.034f, 2.119f, 1.937f};
    float cT[3], sT[3];
#pragma unroll
    for (int i = 0; i < 3; i++) { cT[i] = cosf(TA[i]); sT[i] = sinf(TA[i]); }
    float Ax = 0.f, Ay = 0.f, Az = 1.f;
    float Bx = 0.f, By = 1.f, Bz = 0.f;
    float Cx = 1.f, Cy = 0.f, Cz = 0.f;
    out[(0 * BATCH + b) * 3 + 0] = Ax; out[(0 * BATCH + b) * 3 + 1] = Ay; out[(0 * BATCH + b) * 3 + 2] = Az;
    out[(1 * BATCH + b) * 3 + 0] = Bx; out[(1 * BATCH + b) * 3 + 1] = By; out[(1 * BATCH + b) * 3 + 2] = Bz;
    out[(2 * BATCH + b) * 3 + 0] = Cx; out[(2 * BATCH + b) * 3 + 1] = Cy; out[(2 * BATCH + b) * 3 + 2] = Cz;
    for (int s = 0; s < T_LEN - 1; s++) {
        size_t abase = ((size_t)(s + 1) * BATCH + b) * 3;
#pragma unroll
        for (int i = 0; i < 3; i++) {
            float P = g_ang[abase + i];
            float d2x = -RL[i] * cT[i];
            float d2y = RL[i] * cosf(P) * sT[i];
            float d2z = RL[i] * sinf(P) * sT[i];
            float bcx = Cx - Bx, bcy = Cy - By, bcz = Cz - Bz;
            float rn = 1.0f / sqrtf(bcx * bcx + bcy * bcy + bcz * bcz);
            bcx *= rn; bcy *= rn; bcz *= rn;
            float abx = Bx - Ax, aby = By - Ay, abz = Bz - Az;
            float nx = aby * bcz - abz * bcy;
            float ny = abz * bcx - abx * bcz;
            float nz = abx * bcy - aby * bcx;
            float rn2 = 1.0f / sqrtf(nx * nx + ny * ny + nz * nz);
            nx *= rn2; ny *= rn2; nz *= rn2;
            float m1x = ny * bcz - nz * bcy;
            float m1y = nz * bcx - nx * bcz;
            float m1z = nx * bcy - ny * bcx;
            float Dx = bcx * d2x + m1x * d2y + nx * d2z + Cx;
            float Dy = bcy * d2x + m1y * d2y + ny * d2z + Cy;
            float Dz = bcz * d2x + m1z * d2y + nz * d2z + Cz;
            size_t obase = ((size_t)(3 + 3 * s + i) * BATCH + b) * 3;
            out[obase + 0] = Dx; out[obase + 1] = Dy; out[obase + 2] = Dz;
            Ax = Bx; Ay = By; Az = Bz;
            Bx = Cx; By = Cy; Bz = Cz;
            Cx = Dx; Cy = Dy; Cz = Dz;
        }
    }
}

// ---------------- launch ----------------
extern "C" void kernel_launch(void* const* d_in, const int* in_sizes, int n_in,
                              void* d_out, int out_size) {
    const float* seq   = (const float*)d_in[0];
    const float* w_ih0 = (const float*)d_in[2];
    const float* w_hh0 = (const float*)d_in[3];
    const float* b0    = (const float*)d_in[4];
    const float* w_ih1 = (const float*)d_in[5];
    const float* w_hh1 = (const float*)d_in[6];
    const float* b1    = (const float*)d_in[7];
    const float* lin_w = (const float*)d_in[8];
    const float* lin_b = (const float*)d_in[9];
    const float* alpha = (const float*)d_in[10];
    float* out = (float*)d_out;

    static int smem_set = 0;
    if (!smem_set) {
        cudaFuncSetAttribute(k_lstm_mma, cudaFuncAttributeMaxDynamicSharedMemorySize,
                             LSTM_SMEM);
        smem_set = 1;
    }

    const int n_whh = 2 * G4 * HID;
    const int n_wih1 = NTOT * KTOT;

    k_xw0<<<dim3(G4 / 128, T_LEN, 2), 128>>>(seq, w_ih0, b0);
    k_cvt<<<(n_whh + 255) / 256, 256>>>(w_hh0, 1);
    k_cvt<<<(n_whh + 255) / 256, 256>>>(w_hh1, 2);
    k_cvt<<<(n_wih1 + 255) / 256, 256>>>(w_ih1, 0);
    k_init<<<1, 32>>>();
    k_lstm_mma<<<dim3(HID / 16, 2), 256, LSTM_SMEM>>>(0);
    k_xw1_mma<<<dim3(NTOT / 128, MTOT / 128), 256>>>(b1);
    k_lstm_mma<<<dim3(HID / 16, 2), 256, LSTM_SMEM>>>(1);
    k_head<<<(T_LEN * BATCH) / 8, 256>>>(lin_w, lin_b, alpha);
    k_geom<<<1, 32>>>(out);
}